// round 2
// baseline (speedup 1.0000x reference)
#include <cuda_runtime.h>
#include <cstdint>

// Problem constants (fixed by the dataset)
#define N0 320000
#define N1 80000
#define N2 16000
#define E1 800000
#define E2 160000
#define INC 128
#define F1  256    // H1*HID = 4*64
#define OUTC 48

// ---------------- scratch (static device globals; no runtime allocation) ----
__device__ float g_xl1[(size_t)N0 * F1];   // source transform, layer 1
__device__ float g_xr1[(size_t)N1 * F1];   // target transform, layer 1
__device__ float g_h  [(size_t)N1 * F1];   // relu(layer-1 output)
__device__ float g_xl2[(size_t)N1 * OUTC];
__device__ float g_xr2[(size_t)N2 * OUTC];

__device__ int g_deg1[N1 + 1];
__device__ int g_off1[N1 + 1];
__device__ int g_cur1[N1];
__device__ int g_csr1[E1];        // stores src node id directly
__device__ int g_deg2[N2 + 1];
__device__ int g_off2[N2 + 1];
__device__ int g_cur2[N2];
__device__ int g_csr2[E2];
__device__ int g_bsums[1024];

// ---------------- small utility kernels -------------------------------------
__global__ void zero_int_k(int* p, int n) {
    int i = blockIdx.x * blockDim.x + threadIdx.x;
    if (i < n) p[i] = 0;
}
__global__ void copy_int_k(int* dst, const int* src, int n) {
    int i = blockIdx.x * blockDim.x + threadIdx.x;
    if (i < n) dst[i] = src[i];
}
__global__ void count_k(const int* __restrict__ dst, int* __restrict__ deg, int n) {
    int i = blockIdx.x * blockDim.x + threadIdx.x;
    if (i < n) atomicAdd(&deg[dst[i]], 1);
}
__global__ void scatter_k(const int* __restrict__ src, const int* __restrict__ dst,
                          int* __restrict__ cur, int* __restrict__ csr, int n) {
    int i = blockIdx.x * blockDim.x + threadIdx.x;
    if (i < n) {
        int d = dst[i];
        int pos = atomicAdd(&cur[d], 1);
        csr[pos] = src[i];
    }
}

// Exclusive scan: blockwise (1024 elems/block) + block-sums pass + add pass.
__global__ void scan_block_k(const int* __restrict__ in, int* __restrict__ out,
                             int* __restrict__ bsums, int n) {
    __shared__ int s[1024];
    int tid = threadIdx.x;
    int i = blockIdx.x * 1024 + tid;
    int v = (i < n) ? in[i] : 0;
    s[tid] = v;
    __syncthreads();
    for (int d = 1; d < 1024; d <<= 1) {
        int t = (tid >= d) ? s[tid - d] : 0;
        __syncthreads();
        s[tid] += t;
        __syncthreads();
    }
    if (i < n) out[i] = s[tid] - v;           // exclusive
    if (tid == 1023) bsums[blockIdx.x] = s[1023];
}
__global__ void scan_small_k(int* __restrict__ data, int n) {  // in-place exclusive, 1 block
    __shared__ int s[1024];
    int tid = threadIdx.x;
    int v = (tid < n) ? data[tid] : 0;
    s[tid] = v;
    __syncthreads();
    for (int d = 1; d < 1024; d <<= 1) {
        int t = (tid >= d) ? s[tid - d] : 0;
        __syncthreads();
        s[tid] += t;
        __syncthreads();
    }
    if (tid < n) data[tid] = s[tid] - v;
}
__global__ void scan_add_k(int* __restrict__ out, const int* __restrict__ bsums, int n) {
    int i = blockIdx.x * blockDim.x + threadIdx.x;
    if (i < n) out[i] += bsums[i >> 10];
}

// ---------------- tiled fp32 GEMM: C[M,N] = A[M,K] @ B[K,N] + bias[N] -------
// BM=BN=64, BK=16, 256 threads, 4x4 microtile. M is always a multiple of 64
// for this problem; N may be 48 (< BN) so N is guarded.
__global__ __launch_bounds__(256) void gemm_bias_k(
    const float* __restrict__ A, const float* __restrict__ B,
    const float* __restrict__ bias, float* __restrict__ C,
    int M, int N, int K)
{
    const int BM = 64, BN = 64, BK = 16;
    __shared__ float As[BK][BM + 4];
    __shared__ float Bs[BK][BN];
    int bn = blockIdx.x * BN, bm = blockIdx.y * BM;
    int tx = threadIdx.x & 15, ty = threadIdx.x >> 4;
    float acc[4][4] = {};

    for (int k0 = 0; k0 < K; k0 += BK) {
        #pragma unroll
        for (int t = threadIdx.x; t < BM * BK; t += 256) {
            int m = t >> 4, kk = t & 15;
            As[kk][m] = A[(size_t)(bm + m) * K + k0 + kk];
        }
        #pragma unroll
        for (int t = threadIdx.x; t < BK * BN; t += 256) {
            int kk = t >> 6, nn = t & 63;
            int gn = bn + nn;
            Bs[kk][nn] = (gn < N) ? B[(size_t)(k0 + kk) * N + gn] : 0.f;
        }
        __syncthreads();
        #pragma unroll
        for (int kk = 0; kk < BK; kk++) {
            float4 a4 = *(const float4*)&As[kk][ty * 4];
            float4 b4 = *(const float4*)&Bs[kk][tx * 4];
            float av[4] = {a4.x, a4.y, a4.z, a4.w};
            float bv[4] = {b4.x, b4.y, b4.z, b4.w};
            #pragma unroll
            for (int i = 0; i < 4; i++)
                #pragma unroll
                for (int j = 0; j < 4; j++)
                    acc[i][j] += av[i] * bv[j];
        }
        __syncthreads();
    }
    int gn = bn + tx * 4;
    if (gn < N) {
        float4 bb = *(const float4*)&bias[gn];
        #pragma unroll
        for (int i = 0; i < 4; i++) {
            int gm = bm + ty * 4 + i;
            if (gm < M) {
                float4 o = {acc[i][0] + bb.x, acc[i][1] + bb.y,
                            acc[i][2] + bb.z, acc[i][3] + bb.w};
                *(float4*)&C[(size_t)gm * N + gn] = o;
            }
        }
    }
}

__device__ __forceinline__ float leaky(float v) { return v > 0.f ? v : 0.2f * v; }

// ---------------- layer-1 aggregation: one 64-thread block per dst ----------
// Online softmax over this dst's edges; xl1[src] row read exactly once/edge.
// Thread t owns features [4t, 4t+4) -> entirely within head t>>4.
// 2 edges per iteration to raise memory-level parallelism in the gather.
// Epilogue: +bias1, relu -> h.
__global__ __launch_bounds__(64) void agg1_k(
    const float* __restrict__ xl, const float* __restrict__ xr,
    const int* __restrict__ csr, const int* __restrict__ off,
    const float* __restrict__ att, const float* __restrict__ bias,
    float* __restrict__ out)
{
    int d = blockIdx.x;
    int t = threadIdx.x;
    int base = t * 4;
    float4 attv = *(const float4*)(att + base);
    float4 xrv  = *(const float4*)(xr + (size_t)d * F1 + base);

    float m = -3e38f, l = 0.f;
    float4 acc = {0.f, 0.f, 0.f, 0.f};

    int k0 = off[d], k1 = off[d + 1];
    int k = k0;
    for (; k + 2 <= k1; k += 2) {
        int s0 = csr[k], s1 = csr[k + 1];
        float4 xa = *(const float4*)(xl + (size_t)s0 * F1 + base);
        float4 xb = *(const float4*)(xl + (size_t)s1 * F1 + base);
        float pa = leaky(xa.x + xrv.x) * attv.x + leaky(xa.y + xrv.y) * attv.y
                 + leaky(xa.z + xrv.z) * attv.z + leaky(xa.w + xrv.w) * attv.w;
        float pb = leaky(xb.x + xrv.x) * attv.x + leaky(xb.y + xrv.y) * attv.y
                 + leaky(xb.z + xrv.z) * attv.z + leaky(xb.w + xrv.w) * attv.w;
        #pragma unroll
        for (int o = 8; o; o >>= 1) {
            pa += __shfl_xor_sync(0xffffffffu, pa, o);
            pb += __shfl_xor_sync(0xffffffffu, pb, o);
        }
        float mn = fmaxf(m, fmaxf(pa, pb));
        float sc = __expf(m - mn);
        float ea = __expf(pa - mn);
        float eb = __expf(pb - mn);
        l = l * sc + ea + eb;
        acc.x = acc.x * sc + ea * xa.x + eb * xb.x;
        acc.y = acc.y * sc + ea * xa.y + eb * xb.y;
        acc.z = acc.z * sc + ea * xa.z + eb * xb.z;
        acc.w = acc.w * sc + ea * xa.w + eb * xb.w;
        m = mn;
    }
    if (k < k1) {
        int s = csr[k];
        float4 xv = *(const float4*)(xl + (size_t)s * F1 + base);
        float p = leaky(xv.x + xrv.x) * attv.x + leaky(xv.y + xrv.y) * attv.y
                + leaky(xv.z + xrv.z) * attv.z + leaky(xv.w + xrv.w) * attv.w;
        #pragma unroll
        for (int o = 8; o; o >>= 1) p += __shfl_xor_sync(0xffffffffu, p, o);
        float mn = fmaxf(m, p);
        float sc = __expf(m - mn);
        float pe = __expf(p - mn);
        l = l * sc + pe;
        acc.x = acc.x * sc + pe * xv.x;
        acc.y = acc.y * sc + pe * xv.y;
        acc.z = acc.z * sc + pe * xv.z;
        acc.w = acc.w * sc + pe * xv.w;
        m = mn;
    }
    float inv = 1.f / (l + 1e-16f);
    float4 bv = *(const float4*)(bias + base);
    float4 o;
    o.x = fmaxf(acc.x * inv + bv.x, 0.f);
    o.y = fmaxf(acc.y * inv + bv.y, 0.f);
    o.z = fmaxf(acc.z * inv + bv.z, 0.f);
    o.w = fmaxf(acc.w * inv + bv.w, 0.f);
    *(float4*)(out + (size_t)d * F1 + base) = o;
}

// ---------------- layer-2 aggregation + fused log_softmax -------------------
// One warp per dst node. H=1, C=48: lane owns elem `lane`, and elem `32+lane`
// for lane<16. Online softmax, then log_softmax over the 48-row in-warp.
__global__ __launch_bounds__(128) void agg2_k(
    const float* __restrict__ xl, const float* __restrict__ xr,
    const int* __restrict__ csr, const int* __restrict__ off,
    const float* __restrict__ att, const float* __restrict__ bias,
    float* __restrict__ out, int n)
{
    int w = (blockIdx.x * blockDim.x + threadIdx.x) >> 5;
    if (w >= n) return;
    int lane = threadIdx.x & 31;
    bool lo = (lane < 16);
    float a0 = att[lane];
    float a1 = lo ? att[32 + lane] : 0.f;
    float xr0 = xr[(size_t)w * OUTC + lane];
    float xr1 = lo ? xr[(size_t)w * OUTC + 32 + lane] : 0.f;

    float m = -3e38f, l = 0.f, acc0 = 0.f, acc1 = 0.f;
    int k0 = off[w], k1 = off[w + 1];
    for (int k = k0; k < k1; k++) {
        int s = csr[k];
        float x0 = xl[(size_t)s * OUTC + lane];
        float x1 = lo ? xl[(size_t)s * OUTC + 32 + lane] : 0.f;
        float p = leaky(x0 + xr0) * a0 + leaky(x1 + xr1) * a1;
        #pragma unroll
        for (int o = 16; o; o >>= 1) p += __shfl_xor_sync(0xffffffffu, p, o);
        float mn = fmaxf(m, p);
        float sc = __expf(m - mn);
        float pe = __expf(p - mn);
        l = l * sc + pe;
        acc0 = acc0 * sc + pe * x0;
        acc1 = acc1 * sc + pe * x1;
        m = mn;
    }
    float inv = 1.f / (l + 1e-16f);
    float v0 = acc0 * inv + bias[lane];
    float v1 = lo ? (acc1 * inv + bias[32 + lane]) : -3e38f;

    // log_softmax over 48 values held by this warp
    float mx = fmaxf(v0, v1);
    #pragma unroll
    for (int o = 16; o; o >>= 1) mx = fmaxf(mx, __shfl_xor_sync(0xffffffffu, mx, o));
    float se = __expf(v0 - mx) + (lo ? __expf(v1 - mx) : 0.f);
    #pragma unroll
    for (int o = 16; o; o >>= 1) se += __shfl_xor_sync(0xffffffffu, se, o);
    float lse = logf(se) + mx;
    out[(size_t)w * OUTC + lane] = v0 - lse;
    if (lo) out[(size_t)w * OUTC + 32 + lane] = v1 - lse;
}

// ---------------- host orchestration ----------------------------------------
extern "C" void kernel_launch(void* const* d_in, const int* in_sizes, int n_in,
                              void* d_out, int out_size)
{
    const float* x     = (const float*)d_in[0];
    const float* Wl1   = (const float*)d_in[1];
    const float* bl1   = (const float*)d_in[2];
    const float* Wr1   = (const float*)d_in[3];
    const float* br1   = (const float*)d_in[4];
    const float* att1  = (const float*)d_in[5];
    const float* bias1 = (const float*)d_in[6];
    const float* Wl2   = (const float*)d_in[7];
    const float* bl2   = (const float*)d_in[8];
    const float* Wr2   = (const float*)d_in[9];
    const float* br2   = (const float*)d_in[10];
    const float* att2  = (const float*)d_in[11];
    const float* bias2 = (const float*)d_in[12];
    const int* src1    = (const int*)d_in[13];
    const int* dst1    = (const int*)d_in[14];
    const int* src2    = (const int*)d_in[15];
    const int* dst2    = (const int*)d_in[16];
    float* out = (float*)d_out;

    float *xl1, *xr1, *h, *xl2, *xr2;
    int *deg1, *off1, *cur1, *csr1, *deg2, *off2, *cur2, *csr2, *bsums;
    cudaGetSymbolAddress((void**)&xl1, g_xl1);
    cudaGetSymbolAddress((void**)&xr1, g_xr1);
    cudaGetSymbolAddress((void**)&h,   g_h);
    cudaGetSymbolAddress((void**)&xl2, g_xl2);
    cudaGetSymbolAddress((void**)&xr2, g_xr2);
    cudaGetSymbolAddress((void**)&deg1, g_deg1);
    cudaGetSymbolAddress((void**)&off1, g_off1);
    cudaGetSymbolAddress((void**)&cur1, g_cur1);
    cudaGetSymbolAddress((void**)&csr1, g_csr1);
    cudaGetSymbolAddress((void**)&deg2, g_deg2);
    cudaGetSymbolAddress((void**)&off2, g_off2);
    cudaGetSymbolAddress((void**)&cur2, g_cur2);
    cudaGetSymbolAddress((void**)&csr2, g_csr2);
    cudaGetSymbolAddress((void**)&bsums, g_bsums);

    // layer-1 transforms
    gemm_bias_k<<<dim3((F1 + 63) / 64, (N0 + 63) / 64), 256>>>(x, Wl1, bl1, xl1, N0, F1, INC);
    gemm_bias_k<<<dim3((F1 + 63) / 64, (N1 + 63) / 64), 256>>>(x, Wr1, br1, xr1, N1, F1, INC);

    // CSR by dst, layer 1
    {
        int np = N1 + 1;
        int nb = (np + 1023) / 1024;
        zero_int_k<<<(np + 255) / 256, 256>>>(deg1, np);
        count_k<<<(E1 + 255) / 256, 256>>>(dst1, deg1, E1);
        scan_block_k<<<nb, 1024>>>(deg1, off1, bsums, np);
        scan_small_k<<<1, 1024>>>(bsums, nb);
        scan_add_k<<<(np + 255) / 256, 256>>>(off1, bsums, np);
        copy_int_k<<<(N1 + 255) / 256, 256>>>(cur1, off1, N1);
        scatter_k<<<(E1 + 255) / 256, 256>>>(src1, dst1, cur1, csr1, E1);
    }

    agg1_k<<<N1, 64>>>(xl1, xr1, csr1, off1, att1, bias1, h);

    // layer-2 transforms
    gemm_bias_k<<<dim3((OUTC + 63) / 64, (N1 + 63) / 64), 256>>>(h, Wl2, bl2, xl2, N1, OUTC, F1);
    gemm_bias_k<<<dim3((OUTC + 63) / 64, (N2 + 63) / 64), 256>>>(h, Wr2, br2, xr2, N2, OUTC, F1);

    // CSR by dst, layer 2
    {
        int np = N2 + 1;
        int nb = (np + 1023) / 1024;
        zero_int_k<<<(np + 255) / 256, 256>>>(deg2, np);
        count_k<<<(E2 + 255) / 256, 256>>>(dst2, deg2, E2);
        scan_block_k<<<nb, 1024>>>(deg2, off2, bsums, np);
        scan_small_k<<<1, 1024>>>(bsums, nb);
        scan_add_k<<<(np + 255) / 256, 256>>>(off2, bsums, np);
        copy_int_k<<<(N2 + 255) / 256, 256>>>(cur2, off2, N2);
        scatter_k<<<(E2 + 255) / 256, 256>>>(src2, dst2, cur2, csr2, E2);
    }

    agg2_k<<<N2 / 4, 128>>>(xl2, xr2, csr2, off2, att2, bias2, out, N2);
}

// round 4
// speedup vs baseline: 2.1758x; 2.1758x over previous
#include <cuda_runtime.h>
#include <cuda_fp16.h>
#include <cstdint>

// Problem constants (fixed by the dataset)
#define N0 320000
#define N1 80000
#define N2 16000
#define E1 800000
#define E2 160000
#define INC 128
#define F1  256    // H1*HID = 4*64
#define OUTC 48

// ---------------- scratch (static device globals; no runtime allocation) ----
__device__ float  g_xl1[(size_t)N0 * F1];     // source transform, layer 1 (fp32)
__device__ float  g_xr1[(size_t)N1 * F1];     // target transform, layer 1 (fp32)
__device__ __half g_xh [(size_t)N0 * INC];    // x converted to fp16
__device__ __half g_hh [(size_t)N1 * F1];     // relu(layer-1 out) in fp16
__device__ __half g_w1l[(size_t)F1 * INC];    // Wl1^T as [N,K] fp16
__device__ __half g_w1r[(size_t)F1 * INC];
__device__ __half g_w2l[(size_t)OUTC * F1];
__device__ __half g_w2r[(size_t)OUTC * F1];
__device__ float  g_xl2[(size_t)N1 * OUTC];
__device__ float  g_xr2[(size_t)N2 * OUTC];

__device__ int g_deg1[N1 + 1];
__device__ int g_off1[N1 + 1];
__device__ int g_cur1[N1];
__device__ int g_csr1[E1];
__device__ int g_deg2[N2 + 1];
__device__ int g_off2[N2 + 1];
__device__ int g_cur2[N2];
__device__ int g_csr2[E2];
__device__ int g_bsums[1024];

// ---------------- helpers ----------------------------------------------------
__device__ __forceinline__ uint32_t smem_to_u32(const void* p) {
    uint32_t a;
    asm("{ .reg .u64 t; cvta.to.shared.u64 t, %1; cvt.u32.u64 %0, t; }" : "=r"(a) : "l"(p));
    return a;
}
__device__ __forceinline__ void ldm_x4(uint32_t* r, uint32_t addr) {
    asm volatile("ldmatrix.sync.aligned.m8n8.x4.shared.b16 {%0,%1,%2,%3}, [%4];"
                 : "=r"(r[0]), "=r"(r[1]), "=r"(r[2]), "=r"(r[3]) : "r"(addr));
}
__device__ __forceinline__ void ldm_x2(uint32_t* r, uint32_t addr) {
    asm volatile("ldmatrix.sync.aligned.m8n8.x2.shared.b16 {%0,%1}, [%2];"
                 : "=r"(r[0]), "=r"(r[1]) : "r"(addr));
}
__device__ __forceinline__ void mma16816(float* c, const uint32_t* a, const uint32_t* b) {
    asm volatile("mma.sync.aligned.m16n8k16.row.col.f32.f16.f16.f32 "
                 "{%0,%1,%2,%3}, {%4,%5,%6,%7}, {%8,%9}, {%0,%1,%2,%3};"
                 : "+f"(c[0]), "+f"(c[1]), "+f"(c[2]), "+f"(c[3])
                 : "r"(a[0]), "r"(a[1]), "r"(a[2]), "r"(a[3]), "r"(b[0]), "r"(b[1]));
}

// ---------------- small utility kernels -------------------------------------
__global__ void zero_int_k(int* p, int n) {
    int i = blockIdx.x * blockDim.x + threadIdx.x;
    if (i < n) p[i] = 0;
}
__global__ void copy_int_k(int* dst, const int* src, int n) {
    int i = blockIdx.x * blockDim.x + threadIdx.x;
    if (i < n) dst[i] = src[i];
}
__global__ void count_k(const int* __restrict__ dst, int* __restrict__ deg, int n) {
    int i = blockIdx.x * blockDim.x + threadIdx.x;
    if (i < n) atomicAdd(&deg[dst[i]], 1);
}
__global__ void scatter_k(const int* __restrict__ src, const int* __restrict__ dst,
                          int* __restrict__ cur, int* __restrict__ csr, int n) {
    int i = blockIdx.x * blockDim.x + threadIdx.x;
    if (i < n) {
        int d = dst[i];
        int pos = atomicAdd(&cur[d], 1);
        csr[pos] = src[i];
    }
}
__global__ void scan_block_k(const int* __restrict__ in, int* __restrict__ out,
                             int* __restrict__ bsums, int n) {
    __shared__ int s[1024];
    int tid = threadIdx.x;
    int i = blockIdx.x * 1024 + tid;
    int v = (i < n) ? in[i] : 0;
    s[tid] = v;
    __syncthreads();
    for (int d = 1; d < 1024; d <<= 1) {
        int t = (tid >= d) ? s[tid - d] : 0;
        __syncthreads();
        s[tid] += t;
        __syncthreads();
    }
    if (i < n) out[i] = s[tid] - v;
    if (tid == 1023) bsums[blockIdx.x] = s[1023];
}
__global__ void scan_small_k(int* __restrict__ data, int n) {
    __shared__ int s[1024];
    int tid = threadIdx.x;
    int v = (tid < n) ? data[tid] : 0;
    s[tid] = v;
    __syncthreads();
    for (int d = 1; d < 1024; d <<= 1) {
        int t = (tid >= d) ? s[tid - d] : 0;
        __syncthreads();
        s[tid] += t;
        __syncthreads();
    }
    if (tid < n) data[tid] = s[tid] - v;
}
__global__ void scan_add_k(int* __restrict__ out, const int* __restrict__ bsums, int n) {
    int i = blockIdx.x * blockDim.x + threadIdx.x;
    if (i < n) out[i] += bsums[i >> 10];
}

// fp32 -> fp16 convert (n4 = count of float4 groups)
__global__ void f2h_k(const float* __restrict__ in, __half* __restrict__ out, int n4) {
    int i = blockIdx.x * blockDim.x + threadIdx.x;
    if (i < n4) {
        float4 v = ((const float4*)in)[i];
        __half2* o = (__half2*)out + 2 * (size_t)i;
        o[0] = __floats2half2_rn(v.x, v.y);
        o[1] = __floats2half2_rn(v.z, v.w);
    }
}
// W[K,N] fp32 -> Wt[N,K] fp16
__global__ void wt_k(const float* __restrict__ W, __half* __restrict__ Wt, int K, int N) {
    int i = blockIdx.x * blockDim.x + threadIdx.x;
    if (i < N * K) {
        int n = i / K, k = i % K;
        Wt[i] = __float2half(W[(size_t)k * N + n]);
    }
}

// ---------------- HMMA GEMM: C[M,N_OUT] = A[M,K](f16) @ Bt[N_OUT,K]^T + bias
// BM=128, BK=32, 8 warps (4x2). Warp tile 32 x (BN/2). fp32 accumulate.
// blockIdx.y = M block, blockIdx.x = N block (BN wide).
template<int N_OUT, int K_DIM, int BN>
__global__ __launch_bounds__(256) void hmma_gemm_k(
    const __half* __restrict__ A, const __half* __restrict__ Bt,
    const float* __restrict__ bias, float* __restrict__ C)
{
    constexpr int WN = BN / 2;
    constexpr int NT = WN / 8;
    __shared__ __half As[128][40];
    __shared__ __half Bs[BN][40];

    int tid = threadIdx.x, lane = tid & 31, wid = tid >> 5;
    int wm = wid >> 1, wn = wid & 1;
    size_t m0 = (size_t)blockIdx.y * 128;
    int n0 = blockIdx.x * BN;

    uint32_t asb = smem_to_u32(As), bsb = smem_to_u32(Bs);
    float c[2][NT][4] = {};

    for (int k0 = 0; k0 < K_DIM; k0 += 32) {
        // stage A: 128x32 halves
        #pragma unroll
        for (int i = tid; i < 512; i += 256) {
            int r = i >> 2, cv = i & 3;
            *(uint4*)&As[r][cv * 8] = *(const uint4*)&A[(m0 + r) * K_DIM + k0 + cv * 8];
        }
        // stage B: BN x 32 halves
        #pragma unroll
        for (int i = tid; i < BN * 4; i += 256) {
            int r = i >> 2, cv = i & 3;
            *(uint4*)&Bs[r][cv * 8] = *(const uint4*)&Bt[(size_t)(n0 + r) * K_DIM + k0 + cv * 8];
        }
        __syncthreads();

        #pragma unroll
        for (int kk = 0; kk < 2; kk++) {
            uint32_t af[2][4], bf[NT][2];
            #pragma unroll
            for (int mt = 0; mt < 2; mt++) {
                int row = wm * 32 + mt * 16 + (lane & 7) + ((lane >> 3) & 1) * 8;
                int col = kk * 16 + (lane >> 4) * 8;
                ldm_x4(af[mt], asb + (uint32_t)(row * 40 + col) * 2);
            }
            #pragma unroll
            for (int nt = 0; nt < NT; nt++) {
                int row = wn * WN + nt * 8 + (lane & 7);
                int col = kk * 16 + ((lane >> 3) & 1) * 8;
                ldm_x2(bf[nt], bsb + (uint32_t)(row * 40 + col) * 2);
            }
            #pragma unroll
            for (int mt = 0; mt < 2; mt++)
                #pragma unroll
                for (int nt = 0; nt < NT; nt++)
                    mma16816(c[mt][nt], af[mt], bf[nt]);
        }
        __syncthreads();
    }

    // epilogue: + bias, fp32 store
    #pragma unroll
    for (int mt = 0; mt < 2; mt++) {
        size_t r0 = m0 + wm * 32 + mt * 16 + (lane >> 2);
        #pragma unroll
        for (int nt = 0; nt < NT; nt++) {
            int col = n0 + wn * WN + nt * 8 + (lane & 3) * 2;
            float bx = bias[col], by = bias[col + 1];
            float2 o0 = {c[mt][nt][0] + bx, c[mt][nt][1] + by};
            float2 o1 = {c[mt][nt][2] + bx, c[mt][nt][3] + by};
            *(float2*)&C[r0 * N_OUT + col] = o0;
            *(float2*)&C[(r0 + 8) * N_OUT + col] = o1;
        }
    }
}

__device__ __forceinline__ float leaky(float v) { return v > 0.f ? v : 0.2f * v; }

// ---------------- layer-1 aggregation: one 64-thread block per dst ----------
// Online softmax; writes h directly as fp16 (feeds fp16 GEMM for layer 2).
__global__ __launch_bounds__(64) void agg1_k(
    const float* __restrict__ xl, const float* __restrict__ xr,
    const int* __restrict__ csr, const int* __restrict__ off,
    const float* __restrict__ att, const float* __restrict__ bias,
    __half* __restrict__ out)
{
    int d = blockIdx.x;
    int t = threadIdx.x;
    int base = t * 4;
    float4 attv = *(const float4*)(att + base);
    float4 xrv  = *(const float4*)(xr + (size_t)d * F1 + base);

    float m = -3e38f, l = 0.f;
    float4 acc = {0.f, 0.f, 0.f, 0.f};

    int k0 = off[d], k1 = off[d + 1];
    int k = k0;
    for (; k + 2 <= k1; k += 2) {
        int s0 = csr[k], s1 = csr[k + 1];
        float4 xa = *(const float4*)(xl + (size_t)s0 * F1 + base);
        float4 xb = *(const float4*)(xl + (size_t)s1 * F1 + base);
        float pa = leaky(xa.x + xrv.x) * attv.x + leaky(xa.y + xrv.y) * attv.y
                 + leaky(xa.z + xrv.z) * attv.z + leaky(xa.w + xrv.w) * attv.w;
        float pb = leaky(xb.x + xrv.x) * attv.x + leaky(xb.y + xrv.y) * attv.y
                 + leaky(xb.z + xrv.z) * attv.z + leaky(xb.w + xrv.w) * attv.w;
        #pragma unroll
        for (int o = 8; o; o >>= 1) {
            pa += __shfl_xor_sync(0xffffffffu, pa, o);
            pb += __shfl_xor_sync(0xffffffffu, pb, o);
        }
        float mn = fmaxf(m, fmaxf(pa, pb));
        float sc = __expf(m - mn);
        float ea = __expf(pa - mn);
        float eb = __expf(pb - mn);
        l = l * sc + ea + eb;
        acc.x = acc.x * sc + ea * xa.x + eb * xb.x;
        acc.y = acc.y * sc + ea * xa.y + eb * xb.y;
        acc.z = acc.z * sc + ea * xa.z + eb * xb.z;
        acc.w = acc.w * sc + ea * xa.w + eb * xb.w;
        m = mn;
    }
    if (k < k1) {
        int s = csr[k];
        float4 xv = *(const float4*)(xl + (size_t)s * F1 + base);
        float p = leaky(xv.x + xrv.x) * attv.x + leaky(xv.y + xrv.y) * attv.y
                + leaky(xv.z + xrv.z) * attv.z + leaky(xv.w + xrv.w) * attv.w;
        #pragma unroll
        for (int o = 8; o; o >>= 1) p += __shfl_xor_sync(0xffffffffu, p, o);
        float mn = fmaxf(m, p);
        float sc = __expf(m - mn);
        float pe = __expf(p - mn);
        l = l * sc + pe;
        acc.x = acc.x * sc + pe * xv.x;
        acc.y = acc.y * sc + pe * xv.y;
        acc.z = acc.z * sc + pe * xv.z;
        acc.w = acc.w * sc + pe * xv.w;
        m = mn;
    }
    float inv = 1.f / (l + 1e-16f);
    float4 bv = *(const float4*)(bias + base);
    float ox = fmaxf(acc.x * inv + bv.x, 0.f);
    float oy = fmaxf(acc.y * inv + bv.y, 0.f);
    float oz = fmaxf(acc.z * inv + bv.z, 0.f);
    float ow = fmaxf(acc.w * inv + bv.w, 0.f);
    __half2* hp = (__half2*)(out + (size_t)d * F1 + base);
    hp[0] = __floats2half2_rn(ox, oy);
    hp[1] = __floats2half2_rn(oz, ow);
}

// ---------------- layer-2 aggregation + fused log_softmax -------------------
__global__ __launch_bounds__(128) void agg2_k(
    const float* __restrict__ xl, const float* __restrict__ xr,
    const int* __restrict__ csr, const int* __restrict__ off,
    const float* __restrict__ att, const float* __restrict__ bias,
    float* __restrict__ out, int n)
{
    int w = (blockIdx.x * blockDim.x + threadIdx.x) >> 5;
    if (w >= n) return;
    int lane = threadIdx.x & 31;
    bool lo = (lane < 16);
    float a0 = att[lane];
    float a1 = lo ? att[32 + lane] : 0.f;
    float xr0 = xr[(size_t)w * OUTC + lane];
    float xr1 = lo ? xr[(size_t)w * OUTC + 32 + lane] : 0.f;

    float m = -3e38f, l = 0.f, acc0 = 0.f, acc1 = 0.f;
    int k0 = off[w], k1 = off[w + 1];
    for (int k = k0; k < k1; k++) {
        int s = csr[k];
        float x0 = xl[(size_t)s * OUTC + lane];
        float x1 = lo ? xl[(size_t)s * OUTC + 32 + lane] : 0.f;
        float p = leaky(x0 + xr0) * a0 + leaky(x1 + xr1) * a1;
        #pragma unroll
        for (int o = 16; o; o >>= 1) p += __shfl_xor_sync(0xffffffffu, p, o);
        float mn = fmaxf(m, p);
        float sc = __expf(m - mn);
        float pe = __expf(p - mn);
        l = l * sc + pe;
        acc0 = acc0 * sc + pe * x0;
        acc1 = acc1 * sc + pe * x1;
        m = mn;
    }
    float inv = 1.f / (l + 1e-16f);
    float v0 = acc0 * inv + bias[lane];
    float v1 = lo ? (acc1 * inv + bias[32 + lane]) : -3e38f;

    float mx = fmaxf(v0, v1);
    #pragma unroll
    for (int o = 16; o; o >>= 1) mx = fmaxf(mx, __shfl_xor_sync(0xffffffffu, mx, o));
    float se = __expf(v0 - mx) + (lo ? __expf(v1 - mx) : 0.f);
    #pragma unroll
    for (int o = 16; o; o >>= 1) se += __shfl_xor_sync(0xffffffffu, se, o);
    float lse = logf(se) + mx;
    out[(size_t)w * OUTC + lane] = v0 - lse;
    if (lo) out[(size_t)w * OUTC + 32 + lane] = v1 - lse;
}

// ---------------- host orchestration ----------------------------------------
extern "C" void kernel_launch(void* const* d_in, const int* in_sizes, int n_in,
                              void* d_out, int out_size)
{
    const float* x     = (const float*)d_in[0];
    const float* Wl1   = (const float*)d_in[1];
    const float* bl1   = (const float*)d_in[2];
    const float* Wr1   = (const float*)d_in[3];
    const float* br1   = (const float*)d_in[4];
    const float* att1  = (const float*)d_in[5];
    const float* bias1 = (const float*)d_in[6];
    const float* Wl2   = (const float*)d_in[7];
    const float* bl2   = (const float*)d_in[8];
    const float* Wr2   = (const float*)d_in[9];
    const float* br2   = (const float*)d_in[10];
    const float* att2  = (const float*)d_in[11];
    const float* bias2 = (const float*)d_in[12];
    const int* src1    = (const int*)d_in[13];
    const int* dst1    = (const int*)d_in[14];
    const int* src2    = (const int*)d_in[15];
    const int* dst2    = (const int*)d_in[16];
    float* out = (float*)d_out;

    float *xl1, *xr1, *xl2, *xr2;
    __half *xh, *hh, *w1l, *w1r, *w2l, *w2r;
    int *deg1, *off1, *cur1, *csr1, *deg2, *off2, *cur2, *csr2, *bsums;
    cudaGetSymbolAddress((void**)&xl1, g_xl1);
    cudaGetSymbolAddress((void**)&xr1, g_xr1);
    cudaGetSymbolAddress((void**)&xl2, g_xl2);
    cudaGetSymbolAddress((void**)&xr2, g_xr2);
    cudaGetSymbolAddress((void**)&xh,  g_xh);
    cudaGetSymbolAddress((void**)&hh,  g_hh);
    cudaGetSymbolAddress((void**)&w1l, g_w1l);
    cudaGetSymbolAddress((void**)&w1r, g_w1r);
    cudaGetSymbolAddress((void**)&w2l, g_w2l);
    cudaGetSymbolAddress((void**)&w2r, g_w2r);
    cudaGetSymbolAddress((void**)&deg1, g_deg1);
    cudaGetSymbolAddress((void**)&off1, g_off1);
    cudaGetSymbolAddress((void**)&cur1, g_cur1);
    cudaGetSymbolAddress((void**)&csr1, g_csr1);
    cudaGetSymbolAddress((void**)&deg2, g_deg2);
    cudaGetSymbolAddress((void**)&off2, g_off2);
    cudaGetSymbolAddress((void**)&cur2, g_cur2);
    cudaGetSymbolAddress((void**)&csr2, g_csr2);
    cudaGetSymbolAddress((void**)&bsums, g_bsums);

    // fp16 staging: x and the four weight transposes
    {
        int n4 = (N0 * INC) / 4;
        f2h_k<<<(n4 + 255) / 256, 256>>>(x, xh, n4);
        wt_k<<<(F1 * INC + 255) / 256, 256>>>(Wl1, w1l, INC, F1);
        wt_k<<<(F1 * INC + 255) / 256, 256>>>(Wr1, w1r, INC, F1);
        wt_k<<<(OUTC * F1 + 255) / 256, 256>>>(Wl2, w2l, F1, OUTC);
        wt_k<<<(OUTC * F1 + 255) / 256, 256>>>(Wr2, w2r, F1, OUTC);
    }

    // layer-1 transforms (HMMA tensor cores)
    hmma_gemm_k<F1, INC, 64><<<dim3(F1 / 64, N0 / 128), 256>>>(xh, w1l, bl1, xl1);
    hmma_gemm_k<F1, INC, 64><<<dim3(F1 / 64, N1 / 128), 256>>>(xh, w1r, br1, xr1);

    // CSR by dst, layer 1
    {
        int np = N1 + 1;
        int nb = (np + 1023) / 1024;
        zero_int_k<<<(np + 255) / 256, 256>>>(deg1, np);
        count_k<<<(E1 + 255) / 256, 256>>>(dst1, deg1, E1);
        scan_block_k<<<nb, 1024>>>(deg1, off1, bsums, np);
        scan_small_k<<<1, 1024>>>(bsums, nb);
        scan_add_k<<<(np + 255) / 256, 256>>>(off1, bsums, np);
        copy_int_k<<<(N1 + 255) / 256, 256>>>(cur1, off1, N1);
        scatter_k<<<(E1 + 255) / 256, 256>>>(src1, dst1, cur1, csr1, E1);
    }

    agg1_k<<<N1, 64>>>(xl1, xr1, csr1, off1, att1, bias1, hh);

    // layer-2 transforms (HMMA, fp16 h)
    hmma_gemm_k<OUTC, F1, 48><<<dim3(1, N1 / 128), 256>>>(hh, w2l, bl2, xl2);
    hmma_gemm_k<OUTC, F1, 48><<<dim3(1, N2 / 128), 256>>>(hh, w2r, br2, xr2);

    // CSR by dst, layer 2
    {
        int np = N2 + 1;
        int nb = (np + 1023) / 1024;
        zero_int_k<<<(np + 255) / 256, 256>>>(deg2, np);
        count_k<<<(E2 + 255) / 256, 256>>>(dst2, deg2, E2);
        scan_block_k<<<nb, 1024>>>(deg2, off2, bsums, np);
        scan_small_k<<<1, 1024>>>(bsums, nb);
        scan_add_k<<<(np + 255) / 256, 256>>>(off2, bsums, np);
        copy_int_k<<<(N2 + 255) / 256, 256>>>(cur2, off2, N2);
        scatter_k<<<(E2 + 255) / 256, 256>>>(src2, dst2, cur2, csr2, E2);
    }

    agg2_k<<<N2 / 4, 128>>>(xl2, xr2, csr2, off2, att2, bias2, out, N2);
}

// round 6
// speedup vs baseline: 2.3161x; 1.0645x over previous
#include <cuda_runtime.h>
#include <cuda_fp16.h>
#include <cstdint>

// Problem constants (fixed by the dataset)
#define N0 320000
#define N1 80000
#define N2 16000
#define E1 800000
#define E2 160000
#define INC 128
#define F1  256    // H1*HID = 4*64
#define OUTC 48

// ---------------- scratch (static device globals; no runtime allocation) ----
__device__ __half g_xl1h[(size_t)N0 * F1];    // source transform, layer 1 (fp16)
__device__ __half g_xr1h[(size_t)N1 * F1];    // target transform, layer 1 (fp16)
__device__ __half g_xh [(size_t)N0 * INC];    // x converted to fp16
__device__ __half g_hh [(size_t)N1 * F1];     // relu(layer-1 out) in fp16
__device__ __half g_w1l[(size_t)F1 * INC];    // Wl1^T as [N,K] fp16
__device__ __half g_w1r[(size_t)F1 * INC];
__device__ __half g_w2l[(size_t)OUTC * F1];
__device__ __half g_w2r[(size_t)OUTC * F1];
__device__ float  g_xl2[(size_t)N1 * OUTC];
__device__ float  g_xr2[(size_t)N2 * OUTC];

__device__ int g_deg1[N1 + 1];
__device__ int g_off1[N1 + 1];
__device__ int g_cur1[N1];
__device__ int g_csr1[E1];
__device__ int g_deg2[N2 + 1];
__device__ int g_off2[N2 + 1];
__device__ int g_cur2[N2];
__device__ int g_csr2[E2];
__device__ int g_bsums[1024];

// ---------------- helpers ----------------------------------------------------
__device__ __forceinline__ uint32_t smem_to_u32(const void* p) {
    uint32_t a;
    asm("{ .reg .u64 t; cvta.to.shared.u64 t, %1; cvt.u32.u64 %0, t; }" : "=r"(a) : "l"(p));
    return a;
}
__device__ __forceinline__ void ldm_x4(uint32_t* r, uint32_t addr) {
    asm volatile("ldmatrix.sync.aligned.m8n8.x4.shared.b16 {%0,%1,%2,%3}, [%4];"
                 : "=r"(r[0]), "=r"(r[1]), "=r"(r[2]), "=r"(r[3]) : "r"(addr));
}
__device__ __forceinline__ void ldm_x2(uint32_t* r, uint32_t addr) {
    asm volatile("ldmatrix.sync.aligned.m8n8.x2.shared.b16 {%0,%1}, [%2];"
                 : "=r"(r[0]), "=r"(r[1]) : "r"(addr));
}
__device__ __forceinline__ void mma16816(float* c, const uint32_t* a, const uint32_t* b) {
    asm volatile("mma.sync.aligned.m16n8k16.row.col.f32.f16.f16.f32 "
                 "{%0,%1,%2,%3}, {%4,%5,%6,%7}, {%8,%9}, {%0,%1,%2,%3};"
                 : "+f"(c[0]), "+f"(c[1]), "+f"(c[2]), "+f"(c[3])
                 : "r"(a[0]), "r"(a[1]), "r"(a[2]), "r"(a[3]), "r"(b[0]), "r"(b[1]));
}

// ---------------- small utility kernels -------------------------------------
__global__ void zero_int_k(int* p, int n) {
    int i = blockIdx.x * blockDim.x + threadIdx.x;
    if (i < n) p[i] = 0;
}
__global__ void copy_int_k(int* dst, const int* src, int n) {
    int i = blockIdx.x * blockDim.x + threadIdx.x;
    if (i < n) dst[i] = src[i];
}
__global__ void count_k(const int* __restrict__ dst, int* __restrict__ deg, int n) {
    int i = blockIdx.x * blockDim.x + threadIdx.x;
    if (i < n) atomicAdd(&deg[dst[i]], 1);
}
__global__ void scatter_k(const int* __restrict__ src, const int* __restrict__ dst,
                          int* __restrict__ cur, int* __restrict__ csr, int n) {
    int i = blockIdx.x * blockDim.x + threadIdx.x;
    if (i < n) {
        int d = dst[i];
        int pos = atomicAdd(&cur[d], 1);
        csr[pos] = src[i];
    }
}
__global__ void scan_block_k(const int* __restrict__ in, int* __restrict__ out,
                             int* __restrict__ bsums, int n) {
    __shared__ int s[1024];
    int tid = threadIdx.x;
    int i = blockIdx.x * 1024 + tid;
    int v = (i < n) ? in[i] : 0;
    s[tid] = v;
    __syncthreads();
    for (int d = 1; d < 1024; d <<= 1) {
        int t = (tid >= d) ? s[tid - d] : 0;
        __syncthreads();
        s[tid] += t;
        __syncthreads();
    }
    if (i < n) out[i] = s[tid] - v;
    if (tid == 1023) bsums[blockIdx.x] = s[1023];
}
__global__ void scan_small_k(int* __restrict__ data, int n) {
    __shared__ int s[1024];
    int tid = threadIdx.x;
    int v = (tid < n) ? data[tid] : 0;
    s[tid] = v;
    __syncthreads();
    for (int d = 1; d < 1024; d <<= 1) {
        int t = (tid >= d) ? s[tid - d] : 0;
        __syncthreads();
        s[tid] += t;
        __syncthreads();
    }
    if (tid < n) data[tid] = s[tid] - v;
}
__global__ void scan_add_k(int* __restrict__ out, const int* __restrict__ bsums, int n) {
    int i = blockIdx.x * blockDim.x + threadIdx.x;
    if (i < n) out[i] += bsums[i >> 10];
}

// fp32 -> fp16 convert (n4 = count of float4 groups)
__global__ void f2h_k(const float* __restrict__ in, __half* __restrict__ out, int n4) {
    int i = blockIdx.x * blockDim.x + threadIdx.x;
    if (i < n4) {
        float4 v = ((const float4*)in)[i];
        __half2* o = (__half2*)out + 2 * (size_t)i;
        o[0] = __floats2half2_rn(v.x, v.y);
        o[1] = __floats2half2_rn(v.z, v.w);
    }
}
// W[K,N] fp32 -> Wt[N,K] fp16
__global__ void wt_k(const float* __restrict__ W, __half* __restrict__ Wt, int K, int N) {
    int i = blockIdx.x * blockDim.x + threadIdx.x;
    if (i < N * K) {
        int n = i / K, k = i % K;
        Wt[i] = __float2half(W[(size_t)k * N + n]);
    }
}

// ---------------- HMMA GEMM: C[M,N_OUT] = A[M,K](f16) @ Bt[N_OUT,K]^T + bias
// BM=128, BK=32, 8 warps (4x2). Warp tile 32 x (BN/2). fp32 accumulate.
// HOUT: emit fp16 (half2 stores) instead of fp32.
template<int N_OUT, int K_DIM, int BN, bool HOUT>
__global__ __launch_bounds__(256) void hmma_gemm_k(
    const __half* __restrict__ A, const __half* __restrict__ Bt,
    const float* __restrict__ bias, void* __restrict__ Cv)
{
    constexpr int WN = BN / 2;
    constexpr int NT = WN / 8;
    __shared__ __half As[128][40];
    __shared__ __half Bs[BN][40];

    int tid = threadIdx.x, lane = tid & 31, wid = tid >> 5;
    int wm = wid >> 1, wn = wid & 1;
    size_t m0 = (size_t)blockIdx.y * 128;
    int n0 = blockIdx.x * BN;

    uint32_t asb = smem_to_u32(As), bsb = smem_to_u32(Bs);
    float c[2][NT][4] = {};

    for (int k0 = 0; k0 < K_DIM; k0 += 32) {
        #pragma unroll
        for (int i = tid; i < 512; i += 256) {
            int r = i >> 2, cv = i & 3;
            *(uint4*)&As[r][cv * 8] = *(const uint4*)&A[(m0 + r) * K_DIM + k0 + cv * 8];
        }
        #pragma unroll
        for (int i = tid; i < BN * 4; i += 256) {
            int r = i >> 2, cv = i & 3;
            *(uint4*)&Bs[r][cv * 8] = *(const uint4*)&Bt[(size_t)(n0 + r) * K_DIM + k0 + cv * 8];
        }
        __syncthreads();

        #pragma unroll
        for (int kk = 0; kk < 2; kk++) {
            uint32_t af[2][4], bf[NT][2];
            #pragma unroll
            for (int mt = 0; mt < 2; mt++) {
                int row = wm * 32 + mt * 16 + (lane & 7) + ((lane >> 3) & 1) * 8;
                int col = kk * 16 + (lane >> 4) * 8;
                ldm_x4(af[mt], asb + (uint32_t)(row * 40 + col) * 2);
            }
            #pragma unroll
            for (int nt = 0; nt < NT; nt++) {
                int row = wn * WN + nt * 8 + (lane & 7);
                int col = kk * 16 + ((lane >> 3) & 1) * 8;
                ldm_x2(bf[nt], bsb + (uint32_t)(row * 40 + col) * 2);
            }
            #pragma unroll
            for (int mt = 0; mt < 2; mt++)
                #pragma unroll
                for (int nt = 0; nt < NT; nt++)
                    mma16816(c[mt][nt], af[mt], bf[nt]);
        }
        __syncthreads();
    }

    // epilogue: + bias, store (fp16 or fp32)
    #pragma unroll
    for (int mt = 0; mt < 2; mt++) {
        size_t r0 = m0 + wm * 32 + mt * 16 + (lane >> 2);
        #pragma unroll
        for (int nt = 0; nt < NT; nt++) {
            int col = n0 + wn * WN + nt * 8 + (lane & 3) * 2;
            float bx = bias[col], by = bias[col + 1];
            if (HOUT) {
                __half* C = (__half*)Cv;
                *(__half2*)&C[r0 * N_OUT + col] =
                    __floats2half2_rn(c[mt][nt][0] + bx, c[mt][nt][1] + by);
                *(__half2*)&C[(r0 + 8) * N_OUT + col] =
                    __floats2half2_rn(c[mt][nt][2] + bx, c[mt][nt][3] + by);
            } else {
                float* C = (float*)Cv;
                float2 o0 = {c[mt][nt][0] + bx, c[mt][nt][1] + by};
                float2 o1 = {c[mt][nt][2] + bx, c[mt][nt][3] + by};
                *(float2*)&C[r0 * N_OUT + col] = o0;
                *(float2*)&C[(r0 + 8) * N_OUT + col] = o1;
            }
        }
    }
}

__device__ __forceinline__ float leaky(float v) { return v > 0.f ? v : 0.2f * v; }

__device__ __forceinline__ float4 ldrow_h4(const __half* p) {
    // load 4 consecutive halves (8B, aligned) and upconvert
    __half2 h01 = ((const __half2*)p)[0];
    __half2 h23 = ((const __half2*)p)[1];
    float2 f01 = __half22float2(h01);
    float2 f23 = __half22float2(h23);
    return make_float4(f01.x, f01.y, f23.x, f23.y);
}

// ---------------- layer-1 aggregation: one 64-thread block per dst ----------
// fp16 gather (half the traffic), all math fp32; writes h as fp16.
__global__ __launch_bounds__(64) void agg1_k(
    const __half* __restrict__ xl, const __half* __restrict__ xr,
    const int* __restrict__ csr, const int* __restrict__ off,
    const float* __restrict__ att, const float* __restrict__ bias,
    __half* __restrict__ out)
{
    int d = blockIdx.x;
    int t = threadIdx.x;
    int base = t * 4;
    float4 attv = *(const float4*)(att + base);
    float4 xrv  = ldrow_h4(xr + (size_t)d * F1 + base);

    float m = -3e38f, l = 0.f;
    float4 acc = {0.f, 0.f, 0.f, 0.f};

    int k0 = off[d], k1 = off[d + 1];
    int k = k0;
    for (; k + 2 <= k1; k += 2) {
        int s0 = csr[k], s1 = csr[k + 1];
        float4 xa = ldrow_h4(xl + (size_t)s0 * F1 + base);
        float4 xb = ldrow_h4(xl + (size_t)s1 * F1 + base);
        float pa = leaky(xa.x + xrv.x) * attv.x + leaky(xa.y + xrv.y) * attv.y
                 + leaky(xa.z + xrv.z) * attv.z + leaky(xa.w + xrv.w) * attv.w;
        float pb = leaky(xb.x + xrv.x) * attv.x + leaky(xb.y + xrv.y) * attv.y
                 + leaky(xb.z + xrv.z) * attv.z + leaky(xb.w + xrv.w) * attv.w;
        #pragma unroll
        for (int o = 8; o; o >>= 1) {
            pa += __shfl_xor_sync(0xffffffffu, pa, o);
            pb += __shfl_xor_sync(0xffffffffu, pb, o);
        }
        float mn = fmaxf(m, fmaxf(pa, pb));
        float sc = __expf(m - mn);
        float ea = __expf(pa - mn);
        float eb = __expf(pb - mn);
        l = l * sc + ea + eb;
        acc.x = acc.x * sc + ea * xa.x + eb * xb.x;
        acc.y = acc.y * sc + ea * xa.y + eb * xb.y;
        acc.z = acc.z * sc + ea * xa.z + eb * xb.z;
        acc.w = acc.w * sc + ea * xa.w + eb * xb.w;
        m = mn;
    }
    if (k < k1) {
        int s = csr[k];
        float4 xv = ldrow_h4(xl + (size_t)s * F1 + base);
        float p = leaky(xv.x + xrv.x) * attv.x + leaky(xv.y + xrv.y) * attv.y
                + leaky(xv.z + xrv.z) * attv.z + leaky(xv.w + xrv.w) * attv.w;
        #pragma unroll
        for (int o = 8; o; o >>= 1) p += __shfl_xor_sync(0xffffffffu, p, o);
        float mn = fmaxf(m, p);
        float sc = __expf(m - mn);
        float pe = __expf(p - mn);
        l = l * sc + pe;
        acc.x = acc.x * sc + pe * xv.x;
        acc.y = acc.y * sc + pe * xv.y;
        acc.z = acc.z * sc + pe * xv.z;
        acc.w = acc.w * sc + pe * xv.w;
        m = mn;
    }
    float inv = 1.f / (l + 1e-16f);
    float4 bv = *(const float4*)(bias + base);
    float ox = fmaxf(acc.x * inv + bv.x, 0.f);
    float oy = fmaxf(acc.y * inv + bv.y, 0.f);
    float oz = fmaxf(acc.z * inv + bv.z, 0.f);
    float ow = fmaxf(acc.w * inv + bv.w, 0.f);
    __half2* hp = (__half2*)(out + (size_t)d * F1 + base);
    hp[0] = __floats2half2_rn(ox, oy);
    hp[1] = __floats2half2_rn(oz, ow);
}

// ---------------- layer-2 aggregation + fused log_softmax -------------------
__global__ __launch_bounds__(128) void agg2_k(
    const float* __restrict__ xl, const float* __restrict__ xr,
    const int* __restrict__ csr, const int* __restrict__ off,
    const float* __restrict__ att, const float* __restrict__ bias,
    float* __restrict__ out, int n)
{
    int w = (blockIdx.x * blockDim.x + threadIdx.x) >> 5;
    if (w >= n) return;
    int lane = threadIdx.x & 31;
    bool lo = (lane < 16);
    float a0 = att[lane];
    float a1 = lo ? att[32 + lane] : 0.f;
    float xr0 = xr[(size_t)w * OUTC + lane];
    float xr1 = lo ? xr[(size_t)w * OUTC + 32 + lane] : 0.f;

    float m = -3e38f, l = 0.f, acc0 = 0.f, acc1 = 0.f;
    int k0 = off[w], k1 = off[w + 1];
    for (int k = k0; k < k1; k++) {
        int s = csr[k];
        float x0 = xl[(size_t)s * OUTC + lane];
        float x1 = lo ? xl[(size_t)s * OUTC + 32 + lane] : 0.f;
        float p = leaky(x0 + xr0) * a0 + leaky(x1 + xr1) * a1;
        #pragma unroll
        for (int o = 16; o; o >>= 1) p += __shfl_xor_sync(0xffffffffu, p, o);
        float mn = fmaxf(m, p);
        float sc = __expf(m - mn);
        float pe = __expf(p - mn);
        l = l * sc + pe;
        acc0 = acc0 * sc + pe * x0;
        acc1 = acc1 * sc + pe * x1;
        m = mn;
    }
    float inv = 1.f / (l + 1e-16f);
    float v0 = acc0 * inv + bias[lane];
    float v1 = lo ? (acc1 * inv + bias[32 + lane]) : -3e38f;

    float mx = fmaxf(v0, v1);
    #pragma unroll
    for (int o = 16; o; o >>= 1) mx = fmaxf(mx, __shfl_xor_sync(0xffffffffu, mx, o));
    float se = __expf(v0 - mx) + (lo ? __expf(v1 - mx) : 0.f);
    #pragma unroll
    for (int o = 16; o; o >>= 1) se += __shfl_xor_sync(0xffffffffu, se, o);
    float lse = logf(se) + mx;
    out[(size_t)w * OUTC + lane] = v0 - lse;
    if (lo) out[(size_t)w * OUTC + 32 + lane] = v1 - lse;
}

// ---------------- host orchestration ----------------------------------------
extern "C" void kernel_launch(void* const* d_in, const int* in_sizes, int n_in,
                              void* d_out, int out_size)
{
    const float* x     = (const float*)d_in[0];
    const float* Wl1   = (const float*)d_in[1];
    const float* bl1   = (const float*)d_in[2];
    const float* Wr1   = (const float*)d_in[3];
    const float* br1   = (const float*)d_in[4];
    const float* att1  = (const float*)d_in[5];
    const float* bias1 = (const float*)d_in[6];
    const float* Wl2   = (const float*)d_in[7];
    const float* bl2   = (const float*)d_in[8];
    const float* Wr2   = (const float*)d_in[9];
    const float* br2   = (const float*)d_in[10];
    const float* att2  = (const float*)d_in[11];
    const float* bias2 = (const float*)d_in[12];
    const int* src1    = (const int*)d_in[13];
    const int* dst1    = (const int*)d_in[14];
    const int* src2    = (const int*)d_in[15];
    const int* dst2    = (const int*)d_in[16];
    float* out = (float*)d_out;

    float *xl2, *xr2;
    __half *xl1h, *xr1h, *xh, *hh, *w1l, *w1r, *w2l, *w2r;
    int *deg1, *off1, *cur1, *csr1, *deg2, *off2, *cur2, *csr2, *bsums;
    cudaGetSymbolAddress((void**)&xl1h, g_xl1h);
    cudaGetSymbolAddress((void**)&xr1h, g_xr1h);
    cudaGetSymbolAddress((void**)&xl2, g_xl2);
    cudaGetSymbolAddress((void**)&xr2, g_xr2);
    cudaGetSymbolAddress((void**)&xh,  g_xh);
    cudaGetSymbolAddress((void**)&hh,  g_hh);
    cudaGetSymbolAddress((void**)&w1l, g_w1l);
    cudaGetSymbolAddress((void**)&w1r, g_w1r);
    cudaGetSymbolAddress((void**)&w2l, g_w2l);
    cudaGetSymbolAddress((void**)&w2r, g_w2r);
    cudaGetSymbolAddress((void**)&deg1, g_deg1);
    cudaGetSymbolAddress((void**)&off1, g_off1);
    cudaGetSymbolAddress((void**)&cur1, g_cur1);
    cudaGetSymbolAddress((void**)&csr1, g_csr1);
    cudaGetSymbolAddress((void**)&deg2, g_deg2);
    cudaGetSymbolAddress((void**)&off2, g_off2);
    cudaGetSymbolAddress((void**)&cur2, g_cur2);
    cudaGetSymbolAddress((void**)&csr2, g_csr2);
    cudaGetSymbolAddress((void**)&bsums, g_bsums);

    // fp16 staging: x and the four weight transposes
    {
        int n4 = (N0 * INC) / 4;
        f2h_k<<<(n4 + 255) / 256, 256>>>(x, xh, n4);
        wt_k<<<(F1 * INC + 255) / 256, 256>>>(Wl1, w1l, INC, F1);
        wt_k<<<(F1 * INC + 255) / 256, 256>>>(Wr1, w1r, INC, F1);
        wt_k<<<(OUTC * F1 + 255) / 256, 256>>>(Wl2, w2l, F1, OUTC);
        wt_k<<<(OUTC * F1 + 255) / 256, 256>>>(Wr2, w2r, F1, OUTC);
    }

    // layer-1 transforms (HMMA tensor cores, fp16 outputs)
    hmma_gemm_k<F1, INC, 64, true><<<dim3(F1 / 64, N0 / 128), 256>>>(xh, w1l, bl1, xl1h);
    hmma_gemm_k<F1, INC, 64, true><<<dim3(F1 / 64, N1 / 128), 256>>>(xh, w1r, br1, xr1h);

    // CSR by dst, layer 1
    {
        int np = N1 + 1;
        int nb = (np + 1023) / 1024;
        zero_int_k<<<(np + 255) / 256, 256>>>(deg1, np);
        count_k<<<(E1 + 255) / 256, 256>>>(dst1, deg1, E1);
        scan_block_k<<<nb, 1024>>>(deg1, off1, bsums, np);
        scan_small_k<<<1, 1024>>>(bsums, nb);
        scan_add_k<<<(np + 255) / 256, 256>>>(off1, bsums, np);
        copy_int_k<<<(N1 + 255) / 256, 256>>>(cur1, off1, N1);
        scatter_k<<<(E1 + 255) / 256, 256>>>(src1, dst1, cur1, csr1, E1);
    }

    agg1_k<<<N1, 64>>>(xl1h, xr1h, csr1, off1, att1, bias1, hh);

    // layer-2 transforms (HMMA, fp16 h, fp32 outputs)
    hmma_gemm_k<OUTC, F1, 48, false><<<dim3(1, N1 / 128), 256>>>(hh, w2l, bl2, xl2);
    hmma_gemm_k<OUTC, F1, 48, false><<<dim3(1, N2 / 128), 256>>>(hh, w2r, br2, xr2);

    // CSR by dst, layer 2
    {
        int np = N2 + 1;
        int nb = (np + 1023) / 1024;
        zero_int_k<<<(np + 255) / 256, 256>>>(deg2, np);
        count_k<<<(E2 + 255) / 256, 256>>>(dst2, deg2, E2);
        scan_block_k<<<nb, 1024>>>(deg2, off2, bsums, np);
        scan_small_k<<<1, 1024>>>(bsums, nb);
        scan_add_k<<<(np + 255) / 256, 256>>>(off2, bsums, np);
        copy_int_k<<<(N2 + 255) / 256, 256>>>(cur2, off2, N2);
        scatter_k<<<(E2 + 255) / 256, 256>>>(src2, dst2, cur2, csr2, E2);
    }

    agg2_k<<<N2 / 4, 128>>>(xl2, xr2, csr2, off2, att2, bias2, out, N2);
}

// round 7
// speedup vs baseline: 2.3541x; 1.0164x over previous
#include <cuda_runtime.h>
#include <cuda_fp16.h>
#include <cstdint>

// Problem constants (fixed by the dataset)
#define N0 320000
#define N1 80000
#define N2 16000
#define E1 800000
#define E2 160000
#define INC 128
#define F1  256    // H1*HID = 4*64
#define OUTC 48

// ---------------- scratch (static device globals; no runtime allocation) ----
__device__ __half g_xl1h[(size_t)N0 * F1];    // source transform, layer 1 (fp16)
__device__ __half g_xr1h[(size_t)N1 * F1];    // target transform, layer 1 (fp16)
__device__ __half g_hh [(size_t)N1 * F1];     // relu(layer-1 out) in fp16
__device__ __half g_w1l[(size_t)F1 * INC];    // Wl1^T as [N,K] fp16
__device__ __half g_w1r[(size_t)F1 * INC];
__device__ __half g_w2l[(size_t)OUTC * F1];
__device__ __half g_w2r[(size_t)OUTC * F1];
__device__ float  g_xl2[(size_t)N1 * OUTC];
__device__ float  g_xr2[(size_t)N2 * OUTC];

__device__ int g_deg1[N1 + 1];
__device__ int g_off1[N1 + 1];
__device__ int g_cur1[N1];
__device__ int g_csr1[E1];
__device__ int g_deg2[N2 + 1];
__device__ int g_off2[N2 + 1];
__device__ int g_cur2[N2];
__device__ int g_csr2[E2];
__device__ int g_bsums[1024];

// ---------------- helpers ----------------------------------------------------
__device__ __forceinline__ uint32_t smem_to_u32(const void* p) {
    uint32_t a;
    asm("{ .reg .u64 t; cvta.to.shared.u64 t, %1; cvt.u32.u64 %0, t; }" : "=r"(a) : "l"(p));
    return a;
}
__device__ __forceinline__ void ldm_x4(uint32_t* r, uint32_t addr) {
    asm volatile("ldmatrix.sync.aligned.m8n8.x4.shared.b16 {%0,%1,%2,%3}, [%4];"
                 : "=r"(r[0]), "=r"(r[1]), "=r"(r[2]), "=r"(r[3]) : "r"(addr));
}
__device__ __forceinline__ void ldm_x2(uint32_t* r, uint32_t addr) {
    asm volatile("ldmatrix.sync.aligned.m8n8.x2.shared.b16 {%0,%1}, [%2];"
                 : "=r"(r[0]), "=r"(r[1]) : "r"(addr));
}
__device__ __forceinline__ void mma16816(float* c, const uint32_t* a, const uint32_t* b) {
    asm volatile("mma.sync.aligned.m16n8k16.row.col.f32.f16.f16.f32 "
                 "{%0,%1,%2,%3}, {%4,%5,%6,%7}, {%8,%9}, {%0,%1,%2,%3};"
                 : "+f"(c[0]), "+f"(c[1]), "+f"(c[2]), "+f"(c[3])
                 : "r"(a[0]), "r"(a[1]), "r"(a[2]), "r"(a[3]), "r"(b[0]), "r"(b[1]));
}

// ---------------- small utility kernels -------------------------------------
__global__ void zero2_k(int* a, int na, int* b, int nb) {
    int i = blockIdx.x * blockDim.x + threadIdx.x;
    if (i < na) a[i] = 0;
    if (i < nb) b[i] = 0;
}
__global__ void count_k(const int* __restrict__ dst, int* __restrict__ deg, int n) {
    int i = blockIdx.x * blockDim.x + threadIdx.x;
    if (i < n) atomicAdd(&deg[dst[i]], 1);
}
__global__ void scatter_k(const int* __restrict__ src, const int* __restrict__ dst,
                          int* __restrict__ cur, int* __restrict__ csr, int n) {
    int i = blockIdx.x * blockDim.x + threadIdx.x;
    if (i < n) {
        int d = dst[i];
        int pos = atomicAdd(&cur[d], 1);
        csr[pos] = src[i];
    }
}
__global__ void scan_block_k(const int* __restrict__ in, int* __restrict__ out,
                             int* __restrict__ bsums, int n) {
    __shared__ int s[1024];
    int tid = threadIdx.x;
    int i = blockIdx.x * 1024 + tid;
    int v = (i < n) ? in[i] : 0;
    s[tid] = v;
    __syncthreads();
    for (int d = 1; d < 1024; d <<= 1) {
        int t = (tid >= d) ? s[tid - d] : 0;
        __syncthreads();
        s[tid] += t;
        __syncthreads();
    }
    if (i < n) out[i] = s[tid] - v;
    if (tid == 1023) bsums[blockIdx.x] = s[1023];
}
__global__ void scan_small_k(int* __restrict__ data, int n) {
    __shared__ int s[1024];
    int tid = threadIdx.x;
    int v = (tid < n) ? data[tid] : 0;
    s[tid] = v;
    __syncthreads();
    for (int d = 1; d < 1024; d <<= 1) {
        int t = (tid >= d) ? s[tid - d] : 0;
        __syncthreads();
        s[tid] += t;
        __syncthreads();
    }
    if (tid < n) data[tid] = s[tid] - v;
}
// off[i] += bsums[i>>10]; also mirror into cur[] for the scatter pass
__global__ void scan_add_cur_k(int* __restrict__ out, const int* __restrict__ bsums,
                               int* __restrict__ cur, int n, int nnode) {
    int i = blockIdx.x * blockDim.x + threadIdx.x;
    if (i < n) {
        int v = out[i] + bsums[i >> 10];
        out[i] = v;
        if (i < nnode) cur[i] = v;
    }
}

// All four weight transposes (fp32 [K,N] -> fp16 [N,K]) in one kernel.
__global__ void wt_all_k(const float* __restrict__ Wl1, const float* __restrict__ Wr1,
                         const float* __restrict__ Wl2, const float* __restrict__ Wr2,
                         __half* __restrict__ w1l, __half* __restrict__ w1r,
                         __half* __restrict__ w2l, __half* __restrict__ w2r) {
    const int S1 = F1 * INC;    // 32768
    const int S2 = OUTC * F1;   // 12288
    int i = blockIdx.x * blockDim.x + threadIdx.x;
    if (i < S1) {
        int n = i / INC, k = i % INC;
        w1l[i] = __float2half(Wl1[(size_t)k * F1 + n]);
    } else if (i < 2 * S1) {
        int j = i - S1, n = j / INC, k = j % INC;
        w1r[j] = __float2half(Wr1[(size_t)k * F1 + n]);
    } else if (i < 2 * S1 + S2) {
        int j = i - 2 * S1, n = j / F1, k = j % F1;
        w2l[j] = __float2half(Wl2[(size_t)k * OUTC + n]);
    } else if (i < 2 * S1 + 2 * S2) {
        int j = i - 2 * S1 - S2, n = j / F1, k = j % F1;
        w2r[j] = __float2half(Wr2[(size_t)k * OUTC + n]);
    }
}

// ---------------- HMMA GEMM: C[M,N_OUT] = A[M,K] @ Bt[N_OUT,K]^T + bias
// BM=128, BK=32, 8 warps (4x2). Warp tile 32 x (BN/2). fp32 accumulate.
// A32:  A is fp32, converted to fp16 during SMEM staging (fuses f2h).
// HOUT: emit fp16 (half2 stores) instead of fp32.
template<int N_OUT, int K_DIM, int BN, bool A32, bool HOUT>
__global__ __launch_bounds__(256) void hmma_gemm_k(
    const void* __restrict__ Av, const __half* __restrict__ Bt,
    const float* __restrict__ bias, void* __restrict__ Cv)
{
    constexpr int WN = BN / 2;
    constexpr int NT = WN / 8;
    __shared__ __half As[128][40];
    __shared__ __half Bs[BN][40];

    int tid = threadIdx.x, lane = tid & 31, wid = tid >> 5;
    int wm = wid >> 1, wn = wid & 1;
    size_t m0 = (size_t)blockIdx.y * 128;
    int n0 = blockIdx.x * BN;

    uint32_t asb = smem_to_u32(As), bsb = smem_to_u32(Bs);
    float c[2][NT][4] = {};

    for (int k0 = 0; k0 < K_DIM; k0 += 32) {
        // stage A: 128x32 halves (optionally converting from fp32)
        #pragma unroll
        for (int i = tid; i < 512; i += 256) {
            int r = i >> 2, cv = i & 3;
            if (A32) {
                const float* Af = (const float*)Av;
                const float* p = &Af[(m0 + r) * K_DIM + k0 + cv * 8];
                float4 v0 = *(const float4*)p;
                float4 v1 = *(const float4*)(p + 4);
                __half2 h[4] = {__floats2half2_rn(v0.x, v0.y), __floats2half2_rn(v0.z, v0.w),
                                __floats2half2_rn(v1.x, v1.y), __floats2half2_rn(v1.z, v1.w)};
                *(uint4*)&As[r][cv * 8] = *(uint4*)h;
            } else {
                const __half* Ah = (const __half*)Av;
                *(uint4*)&As[r][cv * 8] = *(const uint4*)&Ah[(m0 + r) * K_DIM + k0 + cv * 8];
            }
        }
        // stage B: BN x 32 halves
        #pragma unroll
        for (int i = tid; i < BN * 4; i += 256) {
            int r = i >> 2, cv = i & 3;
            *(uint4*)&Bs[r][cv * 8] = *(const uint4*)&Bt[(size_t)(n0 + r) * K_DIM + k0 + cv * 8];
        }
        __syncthreads();

        #pragma unroll
        for (int kk = 0; kk < 2; kk++) {
            uint32_t af[2][4], bf[NT][2];
            #pragma unroll
            for (int mt = 0; mt < 2; mt++) {
                int row = wm * 32 + mt * 16 + (lane & 7) + ((lane >> 3) & 1) * 8;
                int col = kk * 16 + (lane >> 4) * 8;
                ldm_x4(af[mt], asb + (uint32_t)(row * 40 + col) * 2);
            }
            #pragma unroll
            for (int nt = 0; nt < NT; nt++) {
                int row = wn * WN + nt * 8 + (lane & 7);
                int col = kk * 16 + ((lane >> 3) & 1) * 8;
                ldm_x2(bf[nt], bsb + (uint32_t)(row * 40 + col) * 2);
            }
            #pragma unroll
            for (int mt = 0; mt < 2; mt++)
                #pragma unroll
                for (int nt = 0; nt < NT; nt++)
                    mma16816(c[mt][nt], af[mt], bf[nt]);
        }
        __syncthreads();
    }

    // epilogue: + bias, store (fp16 or fp32)
    #pragma unroll
    for (int mt = 0; mt < 2; mt++) {
        size_t r0 = m0 + wm * 32 + mt * 16 + (lane >> 2);
        #pragma unroll
        for (int nt = 0; nt < NT; nt++) {
            int col = n0 + wn * WN + nt * 8 + (lane & 3) * 2;
            float bx = bias[col], by = bias[col + 1];
            if (HOUT) {
                __half* C = (__half*)Cv;
                *(__half2*)&C[r0 * N_OUT + col] =
                    __floats2half2_rn(c[mt][nt][0] + bx, c[mt][nt][1] + by);
                *(__half2*)&C[(r0 + 8) * N_OUT + col] =
                    __floats2half2_rn(c[mt][nt][2] + bx, c[mt][nt][3] + by);
            } else {
                float* C = (float*)Cv;
                float2 o0 = {c[mt][nt][0] + bx, c[mt][nt][1] + by};
                float2 o1 = {c[mt][nt][2] + bx, c[mt][nt][3] + by};
                *(float2*)&C[r0 * N_OUT + col] = o0;
                *(float2*)&C[(r0 + 8) * N_OUT + col] = o1;
            }
        }
    }
}

__device__ __forceinline__ float leaky(float v) { return v > 0.f ? v : 0.2f * v; }

__device__ __forceinline__ float4 ldrow_h4(const __half* p) {
    __half2 h01 = ((const __half2*)p)[0];
    __half2 h23 = ((const __half2*)p)[1];
    float2 f01 = __half22float2(h01);
    float2 f23 = __half22float2(h23);
    return make_float4(f01.x, f01.y, f23.x, f23.y);
}

// ---------------- layer-1 aggregation: one 64-thread block per dst ----------
// fp16 gather, all math fp32; writes h as fp16.
__global__ __launch_bounds__(64) void agg1_k(
    const __half* __restrict__ xl, const __half* __restrict__ xr,
    const int* __restrict__ csr, const int* __restrict__ off,
    const float* __restrict__ att, const float* __restrict__ bias,
    __half* __restrict__ out)
{
    int d = blockIdx.x;
    int t = threadIdx.x;
    int base = t * 4;
    float4 attv = *(const float4*)(att + base);
    float4 xrv  = ldrow_h4(xr + (size_t)d * F1 + base);

    float m = -3e38f, l = 0.f;
    float4 acc = {0.f, 0.f, 0.f, 0.f};

    int k0 = off[d], k1 = off[d + 1];
    int k = k0;
    for (; k + 2 <= k1; k += 2) {
        int s0 = csr[k], s1 = csr[k + 1];
        float4 xa = ldrow_h4(xl + (size_t)s0 * F1 + base);
        float4 xb = ldrow_h4(xl + (size_t)s1 * F1 + base);
        float pa = leaky(xa.x + xrv.x) * attv.x + leaky(xa.y + xrv.y) * attv.y
                 + leaky(xa.z + xrv.z) * attv.z + leaky(xa.w + xrv.w) * attv.w;
        float pb = leaky(xb.x + xrv.x) * attv.x + leaky(xb.y + xrv.y) * attv.y
                 + leaky(xb.z + xrv.z) * attv.z + leaky(xb.w + xrv.w) * attv.w;
        #pragma unroll
        for (int o = 8; o; o >>= 1) {
            pa += __shfl_xor_sync(0xffffffffu, pa, o);
            pb += __shfl_xor_sync(0xffffffffu, pb, o);
        }
        float mn = fmaxf(m, fmaxf(pa, pb));
        float sc = __expf(m - mn);
        float ea = __expf(pa - mn);
        float eb = __expf(pb - mn);
        l = l * sc + ea + eb;
        acc.x = acc.x * sc + ea * xa.x + eb * xb.x;
        acc.y = acc.y * sc + ea * xa.y + eb * xb.y;
        acc.z = acc.z * sc + ea * xa.z + eb * xb.z;
        acc.w = acc.w * sc + ea * xa.w + eb * xb.w;
        m = mn;
    }
    if (k < k1) {
        int s = csr[k];
        float4 xv = ldrow_h4(xl + (size_t)s * F1 + base);
        float p = leaky(xv.x + xrv.x) * attv.x + leaky(xv.y + xrv.y) * attv.y
                + leaky(xv.z + xrv.z) * attv.z + leaky(xv.w + xrv.w) * attv.w;
        #pragma unroll
        for (int o = 8; o; o >>= 1) p += __shfl_xor_sync(0xffffffffu, p, o);
        float mn = fmaxf(m, p);
        float sc = __expf(m - mn);
        float pe = __expf(p - mn);
        l = l * sc + pe;
        acc.x = acc.x * sc + pe * xv.x;
        acc.y = acc.y * sc + pe * xv.y;
        acc.z = acc.z * sc + pe * xv.z;
        acc.w = acc.w * sc + pe * xv.w;
        m = mn;
    }
    float inv = 1.f / (l + 1e-16f);
    float4 bv = *(const float4*)(bias + base);
    float ox = fmaxf(acc.x * inv + bv.x, 0.f);
    float oy = fmaxf(acc.y * inv + bv.y, 0.f);
    float oz = fmaxf(acc.z * inv + bv.z, 0.f);
    float ow = fmaxf(acc.w * inv + bv.w, 0.f);
    __half2* hp = (__half2*)(out + (size_t)d * F1 + base);
    hp[0] = __floats2half2_rn(ox, oy);
    hp[1] = __floats2half2_rn(oz, ow);
}

// ---------------- layer-2 aggregation + fused log_softmax -------------------
__global__ __launch_bounds__(128) void agg2_k(
    const float* __restrict__ xl, const float* __restrict__ xr,
    const int* __restrict__ csr, const int* __restrict__ off,
    const float* __restrict__ att, const float* __restrict__ bias,
    float* __restrict__ out, int n)
{
    int w = (blockIdx.x * blockDim.x + threadIdx.x) >> 5;
    if (w >= n) return;
    int lane = threadIdx.x & 31;
    bool lo = (lane < 16);
    float a0 = att[lane];
    float a1 = lo ? att[32 + lane] : 0.f;
    float xr0 = xr[(size_t)w * OUTC + lane];
    float xr1 = lo ? xr[(size_t)w * OUTC + 32 + lane] : 0.f;

    float m = -3e38f, l = 0.f, acc0 = 0.f, acc1 = 0.f;
    int k0 = off[w], k1 = off[w + 1];
    for (int k = k0; k < k1; k++) {
        int s = csr[k];
        float x0 = xl[(size_t)s * OUTC + lane];
        float x1 = lo ? xl[(size_t)s * OUTC + 32 + lane] : 0.f;
        float p = leaky(x0 + xr0) * a0 + leaky(x1 + xr1) * a1;
        #pragma unroll
        for (int o = 16; o; o >>= 1) p += __shfl_xor_sync(0xffffffffu, p, o);
        float mn = fmaxf(m, p);
        float sc = __expf(m - mn);
        float pe = __expf(p - mn);
        l = l * sc + pe;
        acc0 = acc0 * sc + pe * x0;
        acc1 = acc1 * sc + pe * x1;
        m = mn;
    }
    float inv = 1.f / (l + 1e-16f);
    float v0 = acc0 * inv + bias[lane];
    float v1 = lo ? (acc1 * inv + bias[32 + lane]) : -3e38f;

    float mx = fmaxf(v0, v1);
    #pragma unroll
    for (int o = 16; o; o >>= 1) mx = fmaxf(mx, __shfl_xor_sync(0xffffffffu, mx, o));
    float se = __expf(v0 - mx) + (lo ? __expf(v1 - mx) : 0.f);
    #pragma unroll
    for (int o = 16; o; o >>= 1) se += __shfl_xor_sync(0xffffffffu, se, o);
    float lse = logf(se) + mx;
    out[(size_t)w * OUTC + lane] = v0 - lse;
    if (lo) out[(size_t)w * OUTC + 32 + lane] = v1 - lse;
}

// ---------------- host orchestration ----------------------------------------
extern "C" void kernel_launch(void* const* d_in, const int* in_sizes, int n_in,
                              void* d_out, int out_size)
{
    const float* x     = (const float*)d_in[0];
    const float* Wl1   = (const float*)d_in[1];
    const float* bl1   = (const float*)d_in[2];
    const float* Wr1   = (const float*)d_in[3];
    const float* br1   = (const float*)d_in[4];
    const float* att1  = (const float*)d_in[5];
    const float* bias1 = (const float*)d_in[6];
    const float* Wl2   = (const float*)d_in[7];
    const float* bl2   = (const float*)d_in[8];
    const float* Wr2   = (const float*)d_in[9];
    const float* br2   = (const float*)d_in[10];
    const float* att2  = (const float*)d_in[11];
    const float* bias2 = (const float*)d_in[12];
    const int* src1    = (const int*)d_in[13];
    const int* dst1    = (const int*)d_in[14];
    const int* src2    = (const int*)d_in[15];
    const int* dst2    = (const int*)d_in[16];
    float* out = (float*)d_out;

    float *xl2, *xr2;
    __half *xl1h, *xr1h, *hh, *w1l, *w1r, *w2l, *w2r;
    int *deg1, *off1, *cur1, *csr1, *deg2, *off2, *cur2, *csr2, *bsums;
    cudaGetSymbolAddress((void**)&xl1h, g_xl1h);
    cudaGetSymbolAddress((void**)&xr1h, g_xr1h);
    cudaGetSymbolAddress((void**)&xl2, g_xl2);
    cudaGetSymbolAddress((void**)&xr2, g_xr2);
    cudaGetSymbolAddress((void**)&hh,  g_hh);
    cudaGetSymbolAddress((void**)&w1l, g_w1l);
    cudaGetSymbolAddress((void**)&w1r, g_w1r);
    cudaGetSymbolAddress((void**)&w2l, g_w2l);
    cudaGetSymbolAddress((void**)&w2r, g_w2r);
    cudaGetSymbolAddress((void**)&deg1, g_deg1);
    cudaGetSymbolAddress((void**)&off1, g_off1);
    cudaGetSymbolAddress((void**)&cur1, g_cur1);
    cudaGetSymbolAddress((void**)&csr1, g_csr1);
    cudaGetSymbolAddress((void**)&deg2, g_deg2);
    cudaGetSymbolAddress((void**)&off2, g_off2);
    cudaGetSymbolAddress((void**)&cur2, g_cur2);
    cudaGetSymbolAddress((void**)&csr2, g_csr2);
    cudaGetSymbolAddress((void**)&bsums, g_bsums);

    // staging: all 4 weight transposes in one kernel; zero both degree arrays
    {
        const int tot = 2 * F1 * INC + 2 * OUTC * F1;   // 90112
        wt_all_k<<<(tot + 255) / 256, 256>>>(Wl1, Wr1, Wl2, Wr2, w1l, w1r, w2l, w2r);
        zero2_k<<<(N1 + 1 + 255) / 256, 256>>>(deg1, N1 + 1, deg2, N2 + 1);
    }

    // layer-1 transforms (HMMA; A staged from fp32 x with fused conversion)
    hmma_gemm_k<F1, INC, 64, true, true><<<dim3(F1 / 64, N0 / 128), 256>>>(x, w1l, bl1, xl1h);
    hmma_gemm_k<F1, INC, 64, true, true><<<dim3(F1 / 64, N1 / 128), 256>>>(x, w1r, br1, xr1h);

    // CSR by dst, layer 1
    {
        int np = N1 + 1;
        int nb = (np + 1023) / 1024;
        count_k<<<(E1 + 255) / 256, 256>>>(dst1, deg1, E1);
        scan_block_k<<<nb, 1024>>>(deg1, off1, bsums, np);
        scan_small_k<<<1, 1024>>>(bsums, nb);
        scan_add_cur_k<<<(np + 255) / 256, 256>>>(off1, bsums, cur1, np, N1);
        scatter_k<<<(E1 + 255) / 256, 256>>>(src1, dst1, cur1, csr1, E1);
    }

    agg1_k<<<N1, 64>>>(xl1h, xr1h, csr1, off1, att1, bias1, hh);

    // layer-2 transforms (HMMA, fp16 h, fp32 outputs)
    hmma_gemm_k<OUTC, F1, 48, false, false><<<dim3(1, N1 / 128), 256>>>(hh, w2l, bl2, xl2);
    hmma_gemm_k<OUTC, F1, 48, false, false><<<dim3(1, N2 / 128), 256>>>(hh, w2r, br2, xr2);

    // CSR by dst, layer 2
    {
        int np = N2 + 1;
        int nb = (np + 1023) / 1024;
        count_k<<<(E2 + 255) / 256, 256>>>(dst2, deg2, E2);
        scan_block_k<<<nb, 1024>>>(deg2, off2, bsums, np);
        scan_small_k<<<1, 1024>>>(bsums, nb);
        scan_add_cur_k<<<(np + 255) / 256, 256>>>(off2, bsums, cur2, np, N2);
        scatter_k<<<(E2 + 255) / 256, 256>>>(src2, dst2, cur2, csr2, E2);
    }

    agg2_k<<<N2 / 4, 128>>>(xl2, xr2, csr2, off2, att2, bias2, out, N2);
}

// round 9
// speedup vs baseline: 2.9357x; 1.2470x over previous
#include <cuda_runtime.h>
#include <cuda_fp16.h>
#include <cstdint>

// Problem constants (fixed by the dataset)
#define N0 320000
#define N1 80000
#define N2 16000
#define E1 800000
#define E2 160000
#define INC 128
#define F1  256    // H1*HID = 4*64
#define OUTC 48

// ---------------- scratch (static device globals; no runtime allocation) ----
__device__ __half g_xl1h[(size_t)N0 * F1];
__device__ __half g_xr1h[(size_t)N1 * F1];
__device__ __half g_hh [(size_t)N1 * F1];
__device__ __half g_w1l[(size_t)F1 * INC];
__device__ __half g_w1r[(size_t)F1 * INC];
__device__ __half g_w2l[(size_t)OUTC * F1];
__device__ __half g_w2r[(size_t)OUTC * F1];
__device__ float  g_xl2[(size_t)N1 * OUTC];
__device__ float  g_xr2[(size_t)N2 * OUTC];

__device__ int g_deg1[N1 + 1];
__device__ int g_off1[N1 + 1];
__device__ int g_cur1[N1];
__device__ int g_csr1[E1];
__device__ int g_deg2[N2 + 1];
__device__ int g_off2[N2 + 1];
__device__ int g_cur2[N2];
__device__ int g_csr2[E2];
__device__ int g_bsums[1024];

// ---------------- helpers ----------------------------------------------------
__device__ __forceinline__ uint32_t smem_to_u32(const void* p) {
    uint32_t a;
    asm("{ .reg .u64 t; cvta.to.shared.u64 t, %1; cvt.u32.u64 %0, t; }" : "=r"(a) : "l"(p));
    return a;
}
__device__ __forceinline__ void ldm_x4(uint32_t* r, uint32_t addr) {
    asm volatile("ldmatrix.sync.aligned.m8n8.x4.shared.b16 {%0,%1,%2,%3}, [%4];"
                 : "=r"(r[0]), "=r"(r[1]), "=r"(r[2]), "=r"(r[3]) : "r"(addr));
}
__device__ __forceinline__ void ldm_x2(uint32_t* r, uint32_t addr) {
    asm volatile("ldmatrix.sync.aligned.m8n8.x2.shared.b16 {%0,%1}, [%2];"
                 : "=r"(r[0]), "=r"(r[1]) : "r"(addr));
}
__device__ __forceinline__ void mma16816(float* c, const uint32_t* a, const uint32_t* b) {
    asm volatile("mma.sync.aligned.m16n8k16.row.col.f32.f16.f16.f32 "
                 "{%0,%1,%2,%3}, {%4,%5,%6,%7}, {%8,%9}, {%0,%1,%2,%3};"
                 : "+f"(c[0]), "+f"(c[1]), "+f"(c[2]), "+f"(c[3])
                 : "r"(a[0]), "r"(a[1]), "r"(a[2]), "r"(a[3]), "r"(b[0]), "r"(b[1]));
}

// ---------------- small utility kernels -------------------------------------
__global__ void zero2_k(int* a, int na, int* b, int nb) {
    int i = blockIdx.x * blockDim.x + threadIdx.x;
    if (i < na) a[i] = 0;
    if (i < nb) b[i] = 0;
}
__global__ void count_k(const int* __restrict__ dst, int* __restrict__ deg, int n) {
    int i = blockIdx.x * blockDim.x + threadIdx.x;
    if (i < n) atomicAdd(&deg[dst[i]], 1);
}
__global__ void scatter_k(const int* __restrict__ src, const int* __restrict__ dst,
                          int* __restrict__ cur, int* __restrict__ csr, int n) {
    int i = blockIdx.x * blockDim.x + threadIdx.x;
    if (i < n) {
        int d = dst[i];
        int pos = atomicAdd(&cur[d], 1);
        csr[pos] = src[i];
    }
}
__global__ void scan_block_k(const int* __restrict__ in, int* __restrict__ out,
                             int* __restrict__ bsums, int n) {
    __shared__ int s[1024];
    int tid = threadIdx.x;
    int i = blockIdx.x * 1024 + tid;
    int v = (i < n) ? in[i] : 0;
    s[tid] = v;
    __syncthreads();
    for (int d = 1; d < 1024; d <<= 1) {
        int t = (tid >= d) ? s[tid - d] : 0;
        __syncthreads();
        s[tid] += t;
        __syncthreads();
    }
    if (i < n) out[i] = s[tid] - v;
    if (tid == 1023) bsums[blockIdx.x] = s[1023];
}
__global__ void scan_small_k(int* __restrict__ data, int n) {
    __shared__ int s[1024];
    int tid = threadIdx.x;
    int v = (tid < n) ? data[tid] : 0;
    s[tid] = v;
    __syncthreads();
    for (int d = 1; d < 1024; d <<= 1) {
        int t = (tid >= d) ? s[tid - d] : 0;
        __syncthreads();
        s[tid] += t;
        __syncthreads();
    }
    if (tid < n) data[tid] = s[tid] - v;
}
__global__ void scan_add_cur_k(int* __restrict__ out, const int* __restrict__ bsums,
                               int* __restrict__ cur, int n, int nnode) {
    int i = blockIdx.x * blockDim.x + threadIdx.x;
    if (i < n) {
        int v = out[i] + bsums[i >> 10];
        out[i] = v;
        if (i < nnode) cur[i] = v;
    }
}

// All four weight transposes (fp32 [K,N] -> fp16 [N,K]) in one kernel.
__global__ void wt_all_k(const float* __restrict__ Wl1, const float* __restrict__ Wr1,
                         const float* __restrict__ Wl2, const float* __restrict__ Wr2,
                         __half* __restrict__ w1l, __half* __restrict__ w1r,
                         __half* __restrict__ w2l, __half* __restrict__ w2r) {
    const int S1 = F1 * INC;
    const int S2 = OUTC * F1;
    int i = blockIdx.x * blockDim.x + threadIdx.x;
    if (i < S1) {
        int n = i / INC, k = i % INC;
        w1l[i] = __float2half(Wl1[(size_t)k * F1 + n]);
    } else if (i < 2 * S1) {
        int j = i - S1, n = j / INC, k = j % INC;
        w1r[j] = __float2half(Wr1[(size_t)k * F1 + n]);
    } else if (i < 2 * S1 + S2) {
        int j = i - 2 * S1, n = j / F1, k = j % F1;
        w2l[j] = __float2half(Wl2[(size_t)k * OUTC + n]);
    } else if (i < 2 * S1 + 2 * S2) {
        int j = i - 2 * S1 - S2, n = j / F1, k = j % F1;
        w2r[j] = __float2half(Wr2[(size_t)k * OUTC + n]);
    }
}

// ---------------- fused layer-1 GEMM ----------------------------------------
// One CTA per 128 rows of x. A (128x128) staged fp32->fp16 ONCE in SMEM.
// 4 B-panel passes: w1l[0:128], w1l[128:256], and for rows<N1 w1r[0:128],
// w1r[128:256]. 8 warps in 4x2 grid, warp tile 32 rows x 64 cols.
// SMEM rows padded to 136 halves (272B) -> conflict-free ldmatrix.
#define ASTRIDE 136
__global__ __launch_bounds__(256) void gemm1_fused_k(
    const float* __restrict__ x,
    const __half* __restrict__ w1l, const __half* __restrict__ w1r,
    const float* __restrict__ bl1, const float* __restrict__ br1,
    __half* __restrict__ xl, __half* __restrict__ xr, int nr_blocks)
{
    extern __shared__ __half sm[];
    __half* As = sm;                       // 128 x ASTRIDE
    __half* Bs = sm + 128 * ASTRIDE;       // 128 x ASTRIDE

    int tid = threadIdx.x, lane = tid & 31, wid = tid >> 5;
    int wm = wid >> 2, wn = wid & 3;       // 2x4 warp grid: wm 0..1 (64 rows), wn 0..3 ... 
    // NOTE: use 4x2 instead: wm 0..3 (32 rows each), wn 0..1 (64 cols each)
    wm = wid >> 1; wn = wid & 1;
    size_t m0 = (size_t)blockIdx.y * 128;

    uint32_t asb = smem_to_u32(As), bsb = smem_to_u32(Bs);

    // stage A once: 128 rows x 128 cols, fp32 -> fp16
    for (int i = tid; i < 2048; i += 256) {
        int r = i >> 4, c8 = (i & 15) * 8;
        const float* p = &x[(m0 + r) * INC + c8];
        float4 v0 = *(const float4*)p;
        float4 v1 = *(const float4*)(p + 4);
        __half2 h[4] = {__floats2half2_rn(v0.x, v0.y), __floats2half2_rn(v0.z, v0.w),
                        __floats2half2_rn(v1.x, v1.y), __floats2half2_rn(v1.z, v1.w)};
        *(uint4*)&As[r * ASTRIDE + c8] = *(uint4*)h;
    }

    int npass = (blockIdx.y < (unsigned)nr_blocks) ? 4 : 2;
    for (int pass = 0; pass < npass; pass++) {
        const __half* B = (pass < 2) ? w1l : w1r;
        const float* bias = (pass < 2) ? bl1 : br1;
        __half* dst = (pass < 2) ? xl : xr;
        int nb = (pass & 1) * 128;         // column offset within 256-wide output

        __syncthreads();                    // prior ldmatrix / A-stage done
        for (int i = tid; i < 2048; i += 256) {
            int r = i >> 4, c8 = (i & 15) * 8;
            *(uint4*)&Bs[r * ASTRIDE + c8] = *(const uint4*)&B[(size_t)(nb + r) * INC + c8];
        }
        __syncthreads();

        float c[2][8][4] = {};
        #pragma unroll
        for (int kk = 0; kk < 8; kk++) {
            uint32_t af[2][4], bf[8][2];
            #pragma unroll
            for (int mt = 0; mt < 2; mt++) {
                int row = wm * 32 + mt * 16 + (lane & 7) + ((lane >> 3) & 1) * 8;
                int col = kk * 16 + (lane >> 4) * 8;
                ldm_x4(af[mt], asb + (uint32_t)(row * ASTRIDE + col) * 2);
            }
            #pragma unroll
            for (int nt = 0; nt < 8; nt++) {
                int row = wn * 64 + nt * 8 + (lane & 7);
                int col = kk * 16 + ((lane >> 3) & 1) * 8;
                ldm_x2(bf[nt], bsb + (uint32_t)(row * ASTRIDE + col) * 2);
            }
            #pragma unroll
            for (int mt = 0; mt < 2; mt++)
                #pragma unroll
                for (int nt = 0; nt < 8; nt++)
                    mma16816(c[mt][nt], af[mt], bf[nt]);
        }

        // epilogue: + bias, fp16 store
        #pragma unroll
        for (int mt = 0; mt < 2; mt++) {
            size_t r0 = m0 + wm * 32 + mt * 16 + (lane >> 2);
            #pragma unroll
            for (int nt = 0; nt < 8; nt++) {
                int col = nb + wn * 64 + nt * 8 + (lane & 3) * 2;
                float bx = bias[col], by = bias[col + 1];
                *(__half2*)&dst[r0 * F1 + col] =
                    __floats2half2_rn(c[mt][nt][0] + bx, c[mt][nt][1] + by);
                *(__half2*)&dst[(r0 + 8) * F1 + col] =
                    __floats2half2_rn(c[mt][nt][2] + bx, c[mt][nt][3] + by);
            }
        }
    }
}

// ---------------- layer-2 HMMA GEMM (fp16 A, fp32 out) ----------------------
template<int N_OUT, int K_DIM, int BN>
__global__ __launch_bounds__(256) void hmma_gemm_k(
    const __half* __restrict__ A, const __half* __restrict__ Bt,
    const float* __restrict__ bias, float* __restrict__ C)
{
    constexpr int WN = BN / 2;
    constexpr int NT = WN / 8;
    __shared__ __half As[128][40];
    __shared__ __half Bs[BN][40];

    int tid = threadIdx.x, lane = tid & 31, wid = tid >> 5;
    int wm = wid >> 1, wn = wid & 1;
    size_t m0 = (size_t)blockIdx.y * 128;
    int n0 = blockIdx.x * BN;

    uint32_t asb = smem_to_u32(As), bsb = smem_to_u32(Bs);
    float c[2][NT][4] = {};

    for (int k0 = 0; k0 < K_DIM; k0 += 32) {
        #pragma unroll
        for (int i = tid; i < 512; i += 256) {
            int r = i >> 2, cv = i & 3;
            *(uint4*)&As[r][cv * 8] = *(const uint4*)&A[(m0 + r) * K_DIM + k0 + cv * 8];
        }
        #pragma unroll
        for (int i = tid; i < BN * 4; i += 256) {
            int r = i >> 2, cv = i & 3;
            *(uint4*)&Bs[r][cv * 8] = *(const uint4*)&Bt[(size_t)(n0 + r) * K_DIM + k0 + cv * 8];
        }
        __syncthreads();

        #pragma unroll
        for (int kk = 0; kk < 2; kk++) {
            uint32_t af[2][4], bf[NT][2];
            #pragma unroll
            for (int mt = 0; mt < 2; mt++) {
                int row = wm * 32 + mt * 16 + (lane & 7) + ((lane >> 3) & 1) * 8;
                int col = kk * 16 + (lane >> 4) * 8;
                ldm_x4(af[mt], asb + (uint32_t)(row * 40 + col) * 2);
            }
            #pragma unroll
            for (int nt = 0; nt < NT; nt++) {
                int row = wn * WN + nt * 8 + (lane & 7);
                int col = kk * 16 + ((lane >> 3) & 1) * 8;
                ldm_x2(bf[nt], bsb + (uint32_t)(row * 40 + col) * 2);
            }
            #pragma unroll
            for (int mt = 0; mt < 2; mt++)
                #pragma unroll
                for (int nt = 0; nt < NT; nt++)
                    mma16816(c[mt][nt], af[mt], bf[nt]);
        }
        __syncthreads();
    }

    #pragma unroll
    for (int mt = 0; mt < 2; mt++) {
        size_t r0 = m0 + wm * 32 + mt * 16 + (lane >> 2);
        #pragma unroll
        for (int nt = 0; nt < NT; nt++) {
            int col = n0 + wn * WN + nt * 8 + (lane & 3) * 2;
            float bx = bias[col], by = bias[col + 1];
            float2 o0 = {c[mt][nt][0] + bx, c[mt][nt][1] + by};
            float2 o1 = {c[mt][nt][2] + bx, c[mt][nt][3] + by};
            *(float2*)&C[r0 * N_OUT + col] = o0;
            *(float2*)&C[(r0 + 8) * N_OUT + col] = o1;
        }
    }
}

__device__ __forceinline__ float leaky(float v) { return v > 0.f ? v : 0.2f * v; }

__device__ __forceinline__ float4 ldrow_h4(const __half* p) {
    __half2 h01 = ((const __half2*)p)[0];
    __half2 h23 = ((const __half2*)p)[1];
    float2 f01 = __half22float2(h01);
    float2 f23 = __half22float2(h23);
    return make_float4(f01.x, f01.y, f23.x, f23.y);
}

// ---------------- layer-1 aggregation: one 64-thread block per dst ----------
// fp16 gather, 4-edge unroll for MLP, all math fp32; writes h as fp16.
__global__ __launch_bounds__(64) void agg1_k(
    const __half* __restrict__ xl, const __half* __restrict__ xr,
    const int* __restrict__ csr, const int* __restrict__ off,
    const float* __restrict__ att, const float* __restrict__ bias,
    __half* __restrict__ out)
{
    int d = blockIdx.x;
    int t = threadIdx.x;
    int base = t * 4;
    float4 attv = *(const float4*)(att + base);
    float4 xrv  = ldrow_h4(xr + (size_t)d * F1 + base);

    float m = -3e38f, l = 0.f;
    float4 acc = {0.f, 0.f, 0.f, 0.f};

    int k0 = off[d], k1 = off[d + 1];
    int k = k0;
    for (; k + 4 <= k1; k += 4) {
        int s0 = csr[k], s1 = csr[k + 1], s2 = csr[k + 2], s3 = csr[k + 3];
        float4 xa = ldrow_h4(xl + (size_t)s0 * F1 + base);
        float4 xb = ldrow_h4(xl + (size_t)s1 * F1 + base);
        float4 xc = ldrow_h4(xl + (size_t)s2 * F1 + base);
        float4 xd = ldrow_h4(xl + (size_t)s3 * F1 + base);
        float pa = leaky(xa.x + xrv.x) * attv.x + leaky(xa.y + xrv.y) * attv.y
                 + leaky(xa.z + xrv.z) * attv.z + leaky(xa.w + xrv.w) * attv.w;
        float pb = leaky(xb.x + xrv.x) * attv.x + leaky(xb.y + xrv.y) * attv.y
                 + leaky(xb.z + xrv.z) * attv.z + leaky(xb.w + xrv.w) * attv.w;
        float pc = leaky(xc.x + xrv.x) * attv.x + leaky(xc.y + xrv.y) * attv.y
                 + leaky(xc.z + xrv.z) * attv.z + leaky(xc.w + xrv.w) * attv.w;
        float pd = leaky(xd.x + xrv.x) * attv.x + leaky(xd.y + xrv.y) * attv.y
                 + leaky(xd.z + xrv.z) * attv.z + leaky(xd.w + xrv.w) * attv.w;
        #pragma unroll
        for (int o = 8; o; o >>= 1) {
            pa += __shfl_xor_sync(0xffffffffu, pa, o);
            pb += __shfl_xor_sync(0xffffffffu, pb, o);
            pc += __shfl_xor_sync(0xffffffffu, pc, o);
            pd += __shfl_xor_sync(0xffffffffu, pd, o);
        }
        float mn = fmaxf(fmaxf(m, fmaxf(pa, pb)), fmaxf(pc, pd));
        float sc = __expf(m - mn);
        float ea = __expf(pa - mn);
        float eb = __expf(pb - mn);
        float ec = __expf(pc - mn);
        float ed = __expf(pd - mn);
        l = l * sc + ea + eb + ec + ed;
        acc.x = acc.x * sc + ea * xa.x + eb * xb.x + ec * xc.x + ed * xd.x;
        acc.y = acc.y * sc + ea * xa.y + eb * xb.y + ec * xc.y + ed * xd.y;
        acc.z = acc.z * sc + ea * xa.z + eb * xb.z + ec * xc.z + ed * xd.z;
        acc.w = acc.w * sc + ea * xa.w + eb * xb.w + ec * xc.w + ed * xd.w;
        m = mn;
    }
    for (; k < k1; k++) {
        int s = csr[k];
        float4 xv = ldrow_h4(xl + (size_t)s * F1 + base);
        float p = leaky(xv.x + xrv.x) * attv.x + leaky(xv.y + xrv.y) * attv.y
                + leaky(xv.z + xrv.z) * attv.z + leaky(xv.w + xrv.w) * attv.w;
        #pragma unroll
        for (int o = 8; o; o >>= 1) p += __shfl_xor_sync(0xffffffffu, p, o);
        float mn = fmaxf(m, p);
        float sc = __expf(m - mn);
        float pe = __expf(p - mn);
        l = l * sc + pe;
        acc.x = acc.x * sc + pe * xv.x;
        acc.y = acc.y * sc + pe * xv.y;
        acc.z = acc.z * sc + pe * xv.z;
        acc.w = acc.w * sc + pe * xv.w;
        m = mn;
    }
    float inv = 1.f / (l + 1e-16f);
    float4 bv = *(const float4*)(bias + base);
    float ox = fmaxf(acc.x * inv + bv.x, 0.f);
    float oy = fmaxf(acc.y * inv + bv.y, 0.f);
    float oz = fmaxf(acc.z * inv + bv.z, 0.f);
    float ow = fmaxf(acc.w * inv + bv.w, 0.f);
    __half2* hp = (__half2*)(out + (size_t)d * F1 + base);
    hp[0] = __floats2half2_rn(ox, oy);
    hp[1] = __floats2half2_rn(oz, ow);
}

// ---------------- layer-2 aggregation + fused log_softmax -------------------
__global__ __launch_bounds__(128) void agg2_k(
    const float* __restrict__ xl, const float* __restrict__ xr,
    const int* __restrict__ csr, const int* __restrict__ off,
    const float* __restrict__ att, const float* __restrict__ bias,
    float* __restrict__ out, int n)
{
    int w = (blockIdx.x * blockDim.x + threadIdx.x) >> 5;
    if (w >= n) return;
    int lane = threadIdx.x & 31;
    bool lo = (lane < 16);
    float a0 = att[lane];
    float a1 = lo ? att[32 + lane] : 0.f;
    float xr0 = xr[(size_t)w * OUTC + lane];
    float xr1 = lo ? xr[(size_t)w * OUTC + 32 + lane] : 0.f;

    float m = -3e38f, l = 0.f, acc0 = 0.f, acc1 = 0.f;
    int k0 = off[w], k1 = off[w + 1];
    for (int k = k0; k < k1; k++) {
        int s = csr[k];
        float x0 = xl[(size_t)s * OUTC + lane];
        float x1 = lo ? xl[(size_t)s * OUTC + 32 + lane] : 0.f;
        float p = leaky(x0 + xr0) * a0 + leaky(x1 + xr1) * a1;
        #pragma unroll
        for (int o = 16; o; o >>= 1) p += __shfl_xor_sync(0xffffffffu, p, o);
        float mn = fmaxf(m, p);
        float sc = __expf(m - mn);
        float pe = __expf(p - mn);
        l = l * sc + pe;
        acc0 = acc0 * sc + pe * x0;
        acc1 = acc1 * sc + pe * x1;
        m = mn;
    }
    float inv = 1.f / (l + 1e-16f);
    float v0 = acc0 * inv + bias[lane];
    float v1 = lo ? (acc1 * inv + bias[32 + lane]) : -3e38f;

    float mx = fmaxf(v0, v1);
    #pragma unroll
    for (int o = 16; o; o >>= 1) mx = fmaxf(mx, __shfl_xor_sync(0xffffffffu, mx, o));
    float se = __expf(v0 - mx) + (lo ? __expf(v1 - mx) : 0.f);
    #pragma unroll
    for (int o = 16; o; o >>= 1) se += __shfl_xor_sync(0xffffffffu, se, o);
    float lse = logf(se) + mx;
    out[(size_t)w * OUTC + lane] = v0 - lse;
    if (lo) out[(size_t)w * OUTC + 32 + lane] = v1 - lse;
}

// ---------------- host orchestration ----------------------------------------
extern "C" void kernel_launch(void* const* d_in, const int* in_sizes, int n_in,
                              void* d_out, int out_size)
{
    const float* x     = (const float*)d_in[0];
    const float* Wl1   = (const float*)d_in[1];
    const float* bl1   = (const float*)d_in[2];
    const float* Wr1   = (const float*)d_in[3];
    const float* br1   = (const float*)d_in[4];
    const float* att1  = (const float*)d_in[5];
    const float* bias1 = (const float*)d_in[6];
    const float* Wl2   = (const float*)d_in[7];
    const float* bl2   = (const float*)d_in[8];
    const float* Wr2   = (const float*)d_in[9];
    const float* br2   = (const float*)d_in[10];
    const float* att2  = (const float*)d_in[11];
    const float* bias2 = (const float*)d_in[12];
    const int* src1    = (const int*)d_in[13];
    const int* dst1    = (const int*)d_in[14];
    const int* src2    = (const int*)d_in[15];
    const int* dst2    = (const int*)d_in[16];
    float* out = (float*)d_out;

    float *xl2, *xr2;
    __half *xl1h, *xr1h, *hh, *w1l, *w1r, *w2l, *w2r;
    int *deg1, *off1, *cur1, *csr1, *deg2, *off2, *cur2, *csr2, *bsums;
    cudaGetSymbolAddress((void**)&xl1h, g_xl1h);
    cudaGetSymbolAddress((void**)&xr1h, g_xr1h);
    cudaGetSymbolAddress((void**)&xl2, g_xl2);
    cudaGetSymbolAddress((void**)&xr2, g_xr2);
    cudaGetSymbolAddress((void**)&hh,  g_hh);
    cudaGetSymbolAddress((void**)&w1l, g_w1l);
    cudaGetSymbolAddress((void**)&w1r, g_w1r);
    cudaGetSymbolAddress((void**)&w2l, g_w2l);
    cudaGetSymbolAddress((void**)&w2r, g_w2r);
    cudaGetSymbolAddress((void**)&deg1, g_deg1);
    cudaGetSymbolAddress((void**)&off1, g_off1);
    cudaGetSymbolAddress((void**)&cur1, g_cur1);
    cudaGetSymbolAddress((void**)&csr1, g_csr1);
    cudaGetSymbolAddress((void**)&deg2, g_deg2);
    cudaGetSymbolAddress((void**)&off2, g_off2);
    cudaGetSymbolAddress((void**)&cur2, g_cur2);
    cudaGetSymbolAddress((void**)&csr2, g_csr2);
    cudaGetSymbolAddress((void**)&bsums, g_bsums);

    // fused layer-1 GEMM needs 69632 B dynamic SMEM
    const int SMEMF = 2 * 128 * ASTRIDE * (int)sizeof(__half);
    cudaFuncSetAttribute(gemm1_fused_k, cudaFuncAttributeMaxDynamicSharedMemorySize, SMEMF);

    // staging: all 4 weight transposes in one kernel; zero both degree arrays
    {
        const int tot = 2 * F1 * INC + 2 * OUTC * F1;
        wt_all_k<<<(tot + 255) / 256, 256>>>(Wl1, Wr1, Wl2, Wr2, w1l, w1r, w2l, w2r);
        zero2_k<<<(N1 + 1 + 255) / 256, 256>>>(deg1, N1 + 1, deg2, N2 + 1);
    }

    // layer-1 transforms: fused xl + xr, A staged once per 128-row tile
    gemm1_fused_k<<<dim3(1, N0 / 128), 256, SMEMF>>>(x, w1l, w1r, bl1, br1,
                                                     xl1h, xr1h, N1 / 128);

    // CSR by dst, layer 1
    {
        int np = N1 + 1;
        int nb = (np + 1023) / 1024;
        count_k<<<(E1 + 255) / 256, 256>>>(dst1, deg1, E1);
        scan_block_k<<<nb, 1024>>>(deg1, off1, bsums, np);
        scan_small_k<<<1, 1024>>>(bsums, nb);
        scan_add_cur_k<<<(np + 255) / 256, 256>>>(off1, bsums, cur1, np, N1);
        scatter_k<<<(E1 + 255) / 256, 256>>>(src1, dst1, cur1, csr1, E1);
    }

    agg1_k<<<N1, 64>>>(xl1h, xr1h, csr1, off1, att1, bias1, hh);

    // layer-2 transforms (HMMA, fp16 h, fp32 outputs)
    hmma_gemm_k<OUTC, F1, 48><<<dim3(1, N1 / 128), 256>>>(hh, w2l, bl2, xl2);
    hmma_gemm_k<OUTC, F1, 48><<<dim3(1, N2 / 128), 256>>>(hh, w2r, br2, xr2);

    // CSR by dst, layer 2
    {
        int np = N2 + 1;
        int nb = (np + 1023) / 1024;
        count_k<<<(E2 + 255) / 256, 256>>>(dst2, deg2, E2);
        scan_block_k<<<nb, 1024>>>(deg2, off2, bsums, np);
        scan_small_k<<<1, 1024>>>(bsums, nb);
        scan_add_cur_k<<<(np + 255) / 256, 256>>>(off2, bsums, cur2, np, N2);
        scatter_k<<<(E2 + 255) / 256, 256>>>(src2, dst2, cur2, csr2, E2);
    }

    agg2_k<<<N2 / 4, 128>>>(xl2, xr2, csr2, off2, att2, bias2, out, N2);
}

// round 11
// speedup vs baseline: 3.0817x; 1.0498x over previous
#include <cuda_runtime.h>
#include <cuda_fp16.h>
#include <cstdint>

// Problem constants (fixed by the dataset)
#define N0 320000
#define N1 80000
#define N2 16000
#define E1 800000
#define E2 160000
#define INC 128
#define F1  256    // H1*HID = 4*64
#define OUTC 48

#define NB1 79     // ceil((N1+1)/1024)
#define NB2 16     // ceil((N2+1)/1024)

// ---------------- scratch (static device globals; no runtime allocation) ----
__device__ __half g_xl1h[(size_t)N0 * F1];
__device__ __half g_xr1h[(size_t)N1 * F1];
__device__ __half g_hh [(size_t)N1 * F1];
__device__ __half g_w1l[(size_t)F1 * INC];
__device__ __half g_w1r[(size_t)F1 * INC];
__device__ __half g_w2l[(size_t)OUTC * F1];
__device__ __half g_w2r[(size_t)OUTC * F1];
__device__ float  g_xl2[(size_t)N1 * OUTC];
__device__ float  g_xr2[(size_t)N2 * OUTC];

__device__ int g_deg1[N1 + 1];
__device__ int g_off1[N1 + 1];
__device__ int g_cur1[N1];
__device__ int g_csr1[E1];
__device__ int g_deg2[N2 + 1];
__device__ int g_off2[N2 + 1];
__device__ int g_cur2[N2];
__device__ int g_csr2[E2];
__device__ int g_bsums[256];   // [0..NB1) layer1, [128..128+NB2) layer2

// ---------------- helpers ----------------------------------------------------
__device__ __forceinline__ uint32_t smem_to_u32(const void* p) {
    uint32_t a;
    asm("{ .reg .u64 t; cvta.to.shared.u64 t, %1; cvt.u32.u64 %0, t; }" : "=r"(a) : "l"(p));
    return a;
}
__device__ __forceinline__ void ldm_x4(uint32_t* r, uint32_t addr) {
    asm volatile("ldmatrix.sync.aligned.m8n8.x4.shared.b16 {%0,%1,%2,%3}, [%4];"
                 : "=r"(r[0]), "=r"(r[1]), "=r"(r[2]), "=r"(r[3]) : "r"(addr));
}
__device__ __forceinline__ void ldm_x2(uint32_t* r, uint32_t addr) {
    asm volatile("ldmatrix.sync.aligned.m8n8.x2.shared.b16 {%0,%1}, [%2];"
                 : "=r"(r[0]), "=r"(r[1]) : "r"(addr));
}
__device__ __forceinline__ void mma16816(float* c, const uint32_t* a, const uint32_t* b) {
    asm volatile("mma.sync.aligned.m16n8k16.row.col.f32.f16.f16.f32 "
                 "{%0,%1,%2,%3}, {%4,%5,%6,%7}, {%8,%9}, {%0,%1,%2,%3};"
                 : "+f"(c[0]), "+f"(c[1]), "+f"(c[2]), "+f"(c[3])
                 : "r"(a[0]), "r"(a[1]), "r"(a[2]), "r"(a[3]), "r"(b[0]), "r"(b[1]));
}

// ---------------- merged CSR-build kernels -----------------------------------
__global__ void zero2_k(int* a, int na, int* b, int nb) {
    int i = blockIdx.x * blockDim.x + threadIdx.x;
    if (i < na) a[i] = 0;
    if (i < nb) b[i] = 0;
}
// count both layers, 4 edges per thread (int4)
__global__ void count_both_k(const int* __restrict__ dst1, const int* __restrict__ dst2,
                             int* __restrict__ deg1, int* __restrict__ deg2) {
    int i = blockIdx.x * blockDim.x + threadIdx.x;
    if (i < E1 / 4) {
        int4 d = ((const int4*)dst1)[i];
        atomicAdd(&deg1[d.x], 1); atomicAdd(&deg1[d.y], 1);
        atomicAdd(&deg1[d.z], 1); atomicAdd(&deg1[d.w], 1);
    } else if (i < E1 / 4 + E2 / 4) {
        int4 d = ((const int4*)dst2)[i - E1 / 4];
        atomicAdd(&deg2[d.x], 1); atomicAdd(&deg2[d.y], 1);
        atomicAdd(&deg2[d.z], 1); atomicAdd(&deg2[d.w], 1);
    }
}
// blockwise exclusive scan over both degree arrays (blocks 0..NB1-1 -> layer1)
__global__ void scan_block_both_k(const int* __restrict__ deg1, int* __restrict__ off1,
                                  const int* __restrict__ deg2, int* __restrict__ off2,
                                  int* __restrict__ bsums) {
    __shared__ int s[1024];
    int b = blockIdx.x;
    const int* in; int* out; int n; int* bs; int bi;
    if (b < NB1) { in = deg1; out = off1; n = N1 + 1; bs = bsums;       bi = b; }
    else         { in = deg2; out = off2; n = N2 + 1; bs = bsums + 128; bi = b - NB1; }
    int tid = threadIdx.x;
    int i = bi * 1024 + tid;
    int v = (i < n) ? in[i] : 0;
    s[tid] = v;
    __syncthreads();
    for (int d = 1; d < 1024; d <<= 1) {
        int t = (tid >= d) ? s[tid - d] : 0;
        __syncthreads();
        s[tid] += t;
        __syncthreads();
    }
    if (i < n) out[i] = s[tid] - v;
    if (tid == 1023) bs[bi] = s[1023];
}
// scan both bsum segments (NB1 and NB2 elements) in one block
__global__ void scan_small_both_k(int* __restrict__ bsums) {
    __shared__ int s[1024];
    int tid = threadIdx.x;
    // segment 1
    int v = (tid < NB1) ? bsums[tid] : 0;
    s[tid] = v;
    __syncthreads();
    for (int d = 1; d < 1024; d <<= 1) {
        int t = (tid >= d) ? s[tid - d] : 0;
        __syncthreads();
        s[tid] += t;
        __syncthreads();
    }
    if (tid < NB1) bsums[tid] = s[tid] - v;
    __syncthreads();
    // segment 2
    int v2 = (tid < NB2) ? bsums[128 + tid] : 0;
    s[tid] = v2;
    __syncthreads();
    for (int d = 1; d < 1024; d <<= 1) {
        int t = (tid >= d) ? s[tid - d] : 0;
        __syncthreads();
        s[tid] += t;
        __syncthreads();
    }
    if (tid < NB2) bsums[128 + tid] = s[tid] - v2;
}
// add block sums; mirror node prefix into cur[] for scatter
__global__ void scan_add_cur_both_k(int* __restrict__ off1, int* __restrict__ cur1,
                                    int* __restrict__ off2, int* __restrict__ cur2,
                                    const int* __restrict__ bsums) {
    int i = blockIdx.x * blockDim.x + threadIdx.x;
    if (i < N1 + 1) {
        int v = off1[i] + bsums[i >> 10];
        off1[i] = v;
        if (i < N1) cur1[i] = v;
    } else if (i < (N1 + 1) + (N2 + 1)) {
        int j = i - (N1 + 1);
        int v = off2[j] + bsums[128 + (j >> 10)];
        off2[j] = v;
        if (j < N2) cur2[j] = v;
    }
}
__global__ void scatter_both_k(const int* __restrict__ src1, const int* __restrict__ dst1,
                               int* __restrict__ cur1, int* __restrict__ csr1,
                               const int* __restrict__ src2, const int* __restrict__ dst2,
                               int* __restrict__ cur2, int* __restrict__ csr2) {
    int i = blockIdx.x * blockDim.x + threadIdx.x;
    if (i < E1) {
        int d = dst1[i];
        int pos = atomicAdd(&cur1[d], 1);
        csr1[pos] = src1[i];
    } else if (i < E1 + E2) {
        int j = i - E1;
        int d = dst2[j];
        int pos = atomicAdd(&cur2[d], 1);
        csr2[pos] = src2[j];
    }
}

// All four weight transposes (fp32 [K,N] -> fp16 [N,K]) in one kernel.
__global__ void wt_all_k(const float* __restrict__ Wl1, const float* __restrict__ Wr1,
                         const float* __restrict__ Wl2, const float* __restrict__ Wr2,
                         __half* __restrict__ w1l, __half* __restrict__ w1r,
                         __half* __restrict__ w2l, __half* __restrict__ w2r) {
    const int S1 = F1 * INC;
    const int S2 = OUTC * F1;
    int i = blockIdx.x * blockDim.x + threadIdx.x;
    if (i < S1) {
        int n = i / INC, k = i % INC;
        w1l[i] = __float2half(Wl1[(size_t)k * F1 + n]);
    } else if (i < 2 * S1) {
        int j = i - S1, n = j / INC, k = j % INC;
        w1r[j] = __float2half(Wr1[(size_t)k * F1 + n]);
    } else if (i < 2 * S1 + S2) {
        int j = i - 2 * S1, n = j / F1, k = j % F1;
        w2l[j] = __float2half(Wl2[(size_t)k * OUTC + n]);
    } else if (i < 2 * S1 + 2 * S2) {
        int j = i - 2 * S1 - S2, n = j / F1, k = j % F1;
        w2r[j] = __float2half(Wr2[(size_t)k * OUTC + n]);
    }
}

// ---------------- fused layer-1 GEMM ----------------------------------------
// One CTA per 128 rows of x; A staged fp32->fp16 once; 4 B-panel passes.
#define ASTRIDE 136
__global__ __launch_bounds__(256) void gemm1_fused_k(
    const float* __restrict__ x,
    const __half* __restrict__ w1l, const __half* __restrict__ w1r,
    const float* __restrict__ bl1, const float* __restrict__ br1,
    __half* __restrict__ xl, __half* __restrict__ xr, int nr_blocks)
{
    extern __shared__ __half sm[];
    __half* As = sm;
    __half* Bs = sm + 128 * ASTRIDE;

    int tid = threadIdx.x, lane = tid & 31, wid = tid >> 5;
    int wm = wid >> 1, wn = wid & 1;
    size_t m0 = (size_t)blockIdx.y * 128;

    uint32_t asb = smem_to_u32(As), bsb = smem_to_u32(Bs);

    for (int i = tid; i < 2048; i += 256) {
        int r = i >> 4, c8 = (i & 15) * 8;
        const float* p = &x[(m0 + r) * INC + c8];
        float4 v0 = *(const float4*)p;
        float4 v1 = *(const float4*)(p + 4);
        __half2 h[4] = {__floats2half2_rn(v0.x, v0.y), __floats2half2_rn(v0.z, v0.w),
                        __floats2half2_rn(v1.x, v1.y), __floats2half2_rn(v1.z, v1.w)};
        *(uint4*)&As[r * ASTRIDE + c8] = *(uint4*)h;
    }

    int npass = (blockIdx.y < (unsigned)nr_blocks) ? 4 : 2;
    for (int pass = 0; pass < npass; pass++) {
        const __half* B = (pass < 2) ? w1l : w1r;
        const float* bias = (pass < 2) ? bl1 : br1;
        __half* dst = (pass < 2) ? xl : xr;
        int nb = (pass & 1) * 128;

        __syncthreads();
        for (int i = tid; i < 2048; i += 256) {
            int r = i >> 4, c8 = (i & 15) * 8;
            *(uint4*)&Bs[r * ASTRIDE + c8] = *(const uint4*)&B[(size_t)(nb + r) * INC + c8];
        }
        __syncthreads();

        float c[2][8][4] = {};
        #pragma unroll
        for (int kk = 0; kk < 8; kk++) {
            uint32_t af[2][4], bf[8][2];
            #pragma unroll
            for (int mt = 0; mt < 2; mt++) {
                int row = wm * 32 + mt * 16 + (lane & 7) + ((lane >> 3) & 1) * 8;
                int col = kk * 16 + (lane >> 4) * 8;
                ldm_x4(af[mt], asb + (uint32_t)(row * ASTRIDE + col) * 2);
            }
            #pragma unroll
            for (int nt = 0; nt < 8; nt++) {
                int row = wn * 64 + nt * 8 + (lane & 7);
                int col = kk * 16 + ((lane >> 3) & 1) * 8;
                ldm_x2(bf[nt], bsb + (uint32_t)(row * ASTRIDE + col) * 2);
            }
            #pragma unroll
            for (int mt = 0; mt < 2; mt++)
                #pragma unroll
                for (int nt = 0; nt < 8; nt++)
                    mma16816(c[mt][nt], af[mt], bf[nt]);
        }

        #pragma unroll
        for (int mt = 0; mt < 2; mt++) {
            size_t r0 = m0 + wm * 32 + mt * 16 + (lane >> 2);
            #pragma unroll
            for (int nt = 0; nt < 8; nt++) {
                int col = nb + wn * 64 + nt * 8 + (lane & 3) * 2;
                float bx = bias[col], by = bias[col + 1];
                *(__half2*)&dst[r0 * F1 + col] =
                    __floats2half2_rn(c[mt][nt][0] + bx, c[mt][nt][1] + by);
                *(__half2*)&dst[(r0 + 8) * F1 + col] =
                    __floats2half2_rn(c[mt][nt][2] + bx, c[mt][nt][3] + by);
            }
        }
    }
}

// ---------------- merged layer-2 GEMM (both xl2 and xr2 in one launch) -------
// N_OUT=48, K=256, BN=48. blockIdx.y < split -> (w2l -> xl2), else (w2r -> xr2)
__global__ __launch_bounds__(256) void hmma_gemm2_k(
    const __half* __restrict__ A,
    const __half* __restrict__ BtL, const __half* __restrict__ BtR,
    const float* __restrict__ biasL, const float* __restrict__ biasR,
    float* __restrict__ CL, float* __restrict__ CR, int split)
{
    constexpr int BN = 48, WN = 24, NT = 3, K_DIM = F1, N_OUT = OUTC;
    __shared__ __half As[128][40];
    __shared__ __half Bs[BN][40];

    int tid = threadIdx.x, lane = tid & 31, wid = tid >> 5;
    int wm = wid >> 1, wn = wid & 1;

    const __half* Bt; const float* bias; float* C; size_t m0;
    if ((int)blockIdx.y < split) { Bt = BtL; bias = biasL; C = CL; m0 = (size_t)blockIdx.y * 128; }
    else                          { Bt = BtR; bias = biasR; C = CR; m0 = (size_t)(blockIdx.y - split) * 128; }

    uint32_t asb = smem_to_u32(As), bsb = smem_to_u32(Bs);
    float c[2][NT][4] = {};

    for (int k0 = 0; k0 < K_DIM; k0 += 32) {
        #pragma unroll
        for (int i = tid; i < 512; i += 256) {
            int r = i >> 2, cv = i & 3;
            *(uint4*)&As[r][cv * 8] = *(const uint4*)&A[(m0 + r) * K_DIM + k0 + cv * 8];
        }
        #pragma unroll
        for (int i = tid; i < BN * 4; i += 256) {
            int r = i >> 2, cv = i & 3;
            *(uint4*)&Bs[r][cv * 8] = *(const uint4*)&Bt[(size_t)r * K_DIM + k0 + cv * 8];
        }
        __syncthreads();

        #pragma unroll
        for (int kk = 0; kk < 2; kk++) {
            uint32_t af[2][4], bf[NT][2];
            #pragma unroll
            for (int mt = 0; mt < 2; mt++) {
                int row = wm * 32 + mt * 16 + (lane & 7) + ((lane >> 3) & 1) * 8;
                int col = kk * 16 + (lane >> 4) * 8;
                ldm_x4(af[mt], asb + (uint32_t)(row * 40 + col) * 2);
            }
            #pragma unroll
            for (int nt = 0; nt < NT; nt++) {
                int row = wn * WN + nt * 8 + (lane & 7);
                int col = kk * 16 + ((lane >> 3) & 1) * 8;
                ldm_x2(bf[nt], bsb + (uint32_t)(row * 40 + col) * 2);
            }
            #pragma unroll
            for (int mt = 0; mt < 2; mt++)
                #pragma unroll
                for (int nt = 0; nt < NT; nt++)
                    mma16816(c[mt][nt], af[mt], bf[nt]);
        }
        __syncthreads();
    }

    #pragma unroll
    for (int mt = 0; mt < 2; mt++) {
        size_t r0 = m0 + wm * 32 + mt * 16 + (lane >> 2);
        #pragma unroll
        for (int nt = 0; nt < NT; nt++) {
            int col = wn * WN + nt * 8 + (lane & 3) * 2;
            float bx = bias[col], by = bias[col + 1];
            float2 o0 = {c[mt][nt][0] + bx, c[mt][nt][1] + by};
            float2 o1 = {c[mt][nt][2] + bx, c[mt][nt][3] + by};
            *(float2*)&C[r0 * N_OUT + col] = o0;
            *(float2*)&C[(r0 + 8) * N_OUT + col] = o1;
        }
    }
}

__device__ __forceinline__ float leaky(float v) { return v > 0.f ? v : 0.2f * v; }

// single 8B load per 4-half row segment
__device__ __forceinline__ float4 ldrow_h4(const __half* p) {
    uint2 u = *(const uint2*)p;
    __half2 h01 = *(__half2*)&u.x;
    __half2 h23 = *(__half2*)&u.y;
    float2 f01 = __half22float2(h01);
    float2 f23 = __half22float2(h23);
    return make_float4(f01.x, f01.y, f23.x, f23.y);
}

// ---------------- layer-1 aggregation: one 64-thread block per dst ----------
__global__ __launch_bounds__(64) void agg1_k(
    const __half* __restrict__ xl, const __half* __restrict__ xr,
    const int* __restrict__ csr, const int* __restrict__ off,
    const float* __restrict__ att, const float* __restrict__ bias,
    __half* __restrict__ out)
{
    int d = blockIdx.x;
    int t = threadIdx.x;
    int base = t * 4;
    float4 attv = *(const float4*)(att + base);
    float4 xrv  = ldrow_h4(xr + (size_t)d * F1 + base);

    float m = -3e38f, l = 0.f;
    float4 acc = {0.f, 0.f, 0.f, 0.f};

    int k0 = off[d], k1 = off[d + 1];
    int k = k0;
    for (; k + 4 <= k1; k += 4) {
        int s0 = csr[k], s1 = csr[k + 1], s2 = csr[k + 2], s3 = csr[k + 3];
        float4 xa = ldrow_h4(xl + (size_t)s0 * F1 + base);
        float4 xb = ldrow_h4(xl + (size_t)s1 * F1 + base);
        float4 xc = ldrow_h4(xl + (size_t)s2 * F1 + base);
        float4 xd = ldrow_h4(xl + (size_t)s3 * F1 + base);
        float pa = leaky(xa.x + xrv.x) * attv.x + leaky(xa.y + xrv.y) * attv.y
                 + leaky(xa.z + xrv.z) * attv.z + leaky(xa.w + xrv.w) * attv.w;
        float pb = leaky(xb.x + xrv.x) * attv.x + leaky(xb.y + xrv.y) * attv.y
                 + leaky(xb.z + xrv.z) * attv.z + leaky(xb.w + xrv.w) * attv.w;
        float pc = leaky(xc.x + xrv.x) * attv.x + leaky(xc.y + xrv.y) * attv.y
                 + leaky(xc.z + xrv.z) * attv.z + leaky(xc.w + xrv.w) * attv.w;
        float pd = leaky(xd.x + xrv.x) * attv.x + leaky(xd.y + xrv.y) * attv.y
                 + leaky(xd.z + xrv.z) * attv.z + leaky(xd.w + xrv.w) * attv.w;
        #pragma unroll
        for (int o = 8; o; o >>= 1) {
            pa += __shfl_xor_sync(0xffffffffu, pa, o);
            pb += __shfl_xor_sync(0xffffffffu, pb, o);
            pc += __shfl_xor_sync(0xffffffffu, pc, o);
            pd += __shfl_xor_sync(0xffffffffu, pd, o);
        }
        float mn = fmaxf(fmaxf(m, fmaxf(pa, pb)), fmaxf(pc, pd));
        float sc = __expf(m - mn);
        float ea = __expf(pa - mn);
        float eb = __expf(pb - mn);
        float ec = __expf(pc - mn);
        float ed = __expf(pd - mn);
        l = l * sc + ea + eb + ec + ed;
        acc.x = acc.x * sc + ea * xa.x + eb * xb.x + ec * xc.x + ed * xd.x;
        acc.y = acc.y * sc + ea * xa.y + eb * xb.y + ec * xc.y + ed * xd.y;
        acc.z = acc.z * sc + ea * xa.z + eb * xb.z + ec * xc.z + ed * xd.z;
        acc.w = acc.w * sc + ea * xa.w + eb * xb.w + ec * xc.w + ed * xd.w;
        m = mn;
    }
    for (; k < k1; k++) {
        int s = csr[k];
        float4 xv = ldrow_h4(xl + (size_t)s * F1 + base);
        float p = leaky(xv.x + xrv.x) * attv.x + leaky(xv.y + xrv.y) * attv.y
                + leaky(xv.z + xrv.z) * attv.z + leaky(xv.w + xrv.w) * attv.w;
        #pragma unroll
        for (int o = 8; o; o >>= 1) p += __shfl_xor_sync(0xffffffffu, p, o);
        float mn = fmaxf(m, p);
        float sc = __expf(m - mn);
        float pe = __expf(p - mn);
        l = l * sc + pe;
        acc.x = acc.x * sc + pe * xv.x;
        acc.y = acc.y * sc + pe * xv.y;
        acc.z = acc.z * sc + pe * xv.z;
        acc.w = acc.w * sc + pe * xv.w;
        m = mn;
    }
    float inv = 1.f / (l + 1e-16f);
    float4 bv = *(const float4*)(bias + base);
    float ox = fmaxf(acc.x * inv + bv.x, 0.f);
    float oy = fmaxf(acc.y * inv + bv.y, 0.f);
    float oz = fmaxf(acc.z * inv + bv.z, 0.f);
    float ow = fmaxf(acc.w * inv + bv.w, 0.f);
    __half2* hp = (__half2*)(out + (size_t)d * F1 + base);
    hp[0] = __floats2half2_rn(ox, oy);
    hp[1] = __floats2half2_rn(oz, ow);
}

// ---------------- layer-2 aggregation + fused log_softmax -------------------
__global__ __launch_bounds__(128) void agg2_k(
    const float* __restrict__ xl, const float* __restrict__ xr,
    const int* __restrict__ csr, const int* __restrict__ off,
    const float* __restrict__ att, const float* __restrict__ bias,
    float* __restrict__ out, int n)
{
    int w = (blockIdx.x * blockDim.x + threadIdx.x) >> 5;
    if (w >= n) return;
    int lane = threadIdx.x & 31;
    bool lo = (lane < 16);
    float a0 = att[lane];
    float a1 = lo ? att[32 + lane] : 0.f;
    float xr0 = xr[(size_t)w * OUTC + lane];
    float xr1 = lo ? xr[(size_t)w * OUTC + 32 + lane] : 0.f;

    float m = -3e38f, l = 0.f, acc0 = 0.f, acc1 = 0.f;
    int k0 = off[w], k1 = off[w + 1];
    for (int k = k0; k < k1; k++) {
        int s = csr[k];
        float x0 = xl[(size_t)s * OUTC + lane];
        float x1 = lo ? xl[(size_t)s * OUTC + 32 + lane] : 0.f;
        float p = leaky(x0 + xr0) * a0 + leaky(x1 + xr1) * a1;
        #pragma unroll
        for (int o = 16; o; o >>= 1) p += __shfl_xor_sync(0xffffffffu, p, o);
        float mn = fmaxf(m, p);
        float sc = __expf(m - mn);
        float pe = __expf(p - mn);
        l = l * sc + pe;
        acc0 = acc0 * sc + pe * x0;
        acc1 = acc1 * sc + pe * x1;
        m = mn;
    }
    float inv = 1.f / (l + 1e-16f);
    float v0 = acc0 * inv + bias[lane];
    float v1 = lo ? (acc1 * inv + bias[32 + lane]) : -3e38f;

    float mx = fmaxf(v0, v1);
    #pragma unroll
    for (int o = 16; o; o >>= 1) mx = fmaxf(mx, __shfl_xor_sync(0xffffffffu, mx, o));
    float se = __expf(v0 - mx) + (lo ? __expf(v1 - mx) : 0.f);
    #pragma unroll
    for (int o = 16; o; o >>= 1) se += __shfl_xor_sync(0xffffffffu, se, o);
    float lse = logf(se) + mx;
    out[(size_t)w * OUTC + lane] = v0 - lse;
    if (lo) out[(size_t)w * OUTC + 32 + lane] = v1 - lse;
}

// ---------------- host orchestration ----------------------------------------
extern "C" void kernel_launch(void* const* d_in, const int* in_sizes, int n_in,
                              void* d_out, int out_size)
{
    const float* x     = (const float*)d_in[0];
    const float* Wl1   = (const float*)d_in[1];
    const float* bl1   = (const float*)d_in[2];
    const float* Wr1   = (const float*)d_in[3];
    const float* br1   = (const float*)d_in[4];
    const float* att1  = (const float*)d_in[5];
    const float* bias1 = (const float*)d_in[6];
    const float* Wl2   = (const float*)d_in[7];
    const float* bl2   = (const float*)d_in[8];
    const float* Wr2   = (const float*)d_in[9];
    const float* br2   = (const float*)d_in[10];
    const float* att2  = (const float*)d_in[11];
    const float* bias2 = (const float*)d_in[12];
    const int* src1    = (const int*)d_in[13];
    const int* dst1    = (const int*)d_in[14];
    const int* src2    = (const int*)d_in[15];
    const int* dst2    = (const int*)d_in[16];
    float* out = (float*)d_out;

    float *xl2, *xr2;
    __half *xl1h, *xr1h, *hh, *w1l, *w1r, *w2l, *w2r;
    int *deg1, *off1, *cur1, *csr1, *deg2, *off2, *cur2, *csr2, *bsums;
    cudaGetSymbolAddress((void**)&xl1h, g_xl1h);
    cudaGetSymbolAddress((void**)&xr1h, g_xr1h);
    cudaGetSymbolAddress((void**)&xl2, g_xl2);
    cudaGetSymbolAddress((void**)&xr2, g_xr2);
    cudaGetSymbolAddress((void**)&hh,  g_hh);
    cudaGetSymbolAddress((void**)&w1l, g_w1l);
    cudaGetSymbolAddress((void**)&w1r, g_w1r);
    cudaGetSymbolAddress((void**)&w2l, g_w2l);
    cudaGetSymbolAddress((void**)&w2r, g_w2r);
    cudaGetSymbolAddress((void**)&deg1, g_deg1);
    cudaGetSymbolAddress((void**)&off1, g_off1);
    cudaGetSymbolAddress((void**)&cur1, g_cur1);
    cudaGetSymbolAddress((void**)&csr1, g_csr1);
    cudaGetSymbolAddress((void**)&deg2, g_deg2);
    cudaGetSymbolAddress((void**)&off2, g_off2);
    cudaGetSymbolAddress((void**)&cur2, g_cur2);
    cudaGetSymbolAddress((void**)&csr2, g_csr2);
    cudaGetSymbolAddress((void**)&bsums, g_bsums);

    const int SMEMF = 2 * 128 * ASTRIDE * (int)sizeof(__half);
    cudaFuncSetAttribute(gemm1_fused_k, cudaFuncAttributeMaxDynamicSharedMemorySize, SMEMF);

    // staging
    {
        const int tot = 2 * F1 * INC + 2 * OUTC * F1;
        wt_all_k<<<(tot + 255) / 256, 256>>>(Wl1, Wr1, Wl2, Wr2, w1l, w1r, w2l, w2r);
        zero2_k<<<(N1 + 1 + 255) / 256, 256>>>(deg1, N1 + 1, deg2, N2 + 1);
    }

    // layer-1 transforms (fused xl + xr)
    gemm1_fused_k<<<dim3(1, N0 / 128), 256, SMEMF>>>(x, w1l, w1r, bl1, br1,
                                                     xl1h, xr1h, N1 / 128);

    // CSR builds for BOTH layers (merged kernels)
    {
        const int ctot = E1 / 4 + E2 / 4;
        count_both_k<<<(ctot + 255) / 256, 256>>>(dst1, dst2, deg1, deg2);
        scan_block_both_k<<<NB1 + NB2, 1024>>>(deg1, off1, deg2, off2, bsums);
        scan_small_both_k<<<1, 1024>>>(bsums);
        const int atot = (N1 + 1) + (N2 + 1);
        scan_add_cur_both_k<<<(atot + 255) / 256, 256>>>(off1, cur1, off2, cur2, bsums);
        scatter_both_k<<<(E1 + E2 + 255) / 256, 256>>>(src1, dst1, cur1, csr1,
                                                       src2, dst2, cur2, csr2);
    }

    agg1_k<<<N1, 64>>>(xl1h, xr1h, csr1, off1, att1, bias1, hh);

    // merged layer-2 GEMMs
    hmma_gemm2_k<<<dim3(1, N1 / 128 + N2 / 128), 256>>>(hh, w2l, w2r, bl2, br2,
                                                        xl2, xr2, N1 / 128);

    agg2_k<<<N2 / 4, 128>>>(xl2, xr2, csr2, off2, att2, bias2, out, N2);
}

// round 13
// speedup vs baseline: 3.1639x; 1.0267x over previous
#include <cuda_runtime.h>
#include <cuda_fp16.h>
#include <cstdint>

// Problem constants (fixed by the dataset)
#define N0 320000
#define N1 80000
#define N2 16000
#define E1 800000
#define E2 160000
#define INC 128
#define F1  256    // H1*HID = 4*64
#define OUTC 48

#define NB1 79     // ceil((N1+1)/1024)
#define NB2 16     // ceil((N2+1)/1024)
#define NGEMM1 (N0 / 128)          // 2500
#define NCNT 235                   // ceil((E1/4 + E2/4) / 1024)

// ---------------- scratch (static device globals; no runtime allocation) ----
__device__ __half g_xl1h[(size_t)N0 * F1];
__device__ __half g_xr1h[(size_t)N1 * F1];
__device__ __half g_hh [(size_t)N1 * F1];
__device__ __half g_w1l[(size_t)F1 * INC];
__device__ __half g_w1r[(size_t)F1 * INC];
__device__ __half g_w2l[(size_t)OUTC * F1];
__device__ __half g_w2r[(size_t)OUTC * F1];
__device__ float  g_xl2[(size_t)N1 * OUTC];
__device__ float  g_xr2[(size_t)N2 * OUTC];

__device__ int g_deg1[N1 + 1];
__device__ int g_off1[N1 + 1];
__device__ int g_cur1[N1];
__device__ int g_csr1[E1];
__device__ int g_deg2[N2 + 1];
__device__ int g_off2[N2 + 1];
__device__ int g_cur2[N2];
__device__ int g_csr2[E2];
__device__ int g_bsums[128];      // per-block aggregates (NB1+NB2 = 95 used)
__device__ int g_flags[128];      // publish flags for lookback scan

// ---------------- helpers ----------------------------------------------------
__device__ __forceinline__ uint32_t smem_to_u32(const void* p) {
    uint32_t a;
    asm("{ .reg .u64 t; cvta.to.shared.u64 t, %1; cvt.u32.u64 %0, t; }" : "=r"(a) : "l"(p));
    return a;
}
__device__ __forceinline__ void ldm_x4(uint32_t* r, uint32_t addr) {
    asm volatile("ldmatrix.sync.aligned.m8n8.x4.shared.b16 {%0,%1,%2,%3}, [%4];"
                 : "=r"(r[0]), "=r"(r[1]), "=r"(r[2]), "=r"(r[3]) : "r"(addr));
}
__device__ __forceinline__ void ldm_x2(uint32_t* r, uint32_t addr) {
    asm volatile("ldmatrix.sync.aligned.m8n8.x2.shared.b16 {%0,%1}, [%2];"
                 : "=r"(r[0]), "=r"(r[1]) : "r"(addr));
}
__device__ __forceinline__ void mma16816(float* c, const uint32_t* a, const uint32_t* b) {
    asm volatile("mma.sync.aligned.m16n8k16.row.col.f32.f16.f16.f32 "
                 "{%0,%1,%2,%3}, {%4,%5,%6,%7}, {%8,%9}, {%0,%1,%2,%3};"
                 : "+f"(c[0]), "+f"(c[1]), "+f"(c[2]), "+f"(c[3])
                 : "r"(a[0]), "r"(a[1]), "r"(a[2]), "r"(a[3]), "r"(b[0]), "r"(b[1]));
}

// ---------------- prep: weight transposes + zero deg/flags (one launch) -----
__global__ void prep_k(const float* __restrict__ Wl1, const float* __restrict__ Wr1,
                       const float* __restrict__ Wl2, const float* __restrict__ Wr2,
                       __half* __restrict__ w1l, __half* __restrict__ w1r,
                       __half* __restrict__ w2l, __half* __restrict__ w2r,
                       int* __restrict__ deg1, int* __restrict__ deg2,
                       int* __restrict__ flags) {
    const int S1 = F1 * INC;     // 32768
    const int S2 = OUTC * F1;    // 12288
    int i = blockIdx.x * blockDim.x + threadIdx.x;
    if (i < S1) {
        int n = i / INC, k = i % INC;
        w1l[i] = __float2half(Wl1[(size_t)k * F1 + n]);
    } else if (i < 2 * S1) {
        int j = i - S1, n = j / INC, k = j % INC;
        w1r[j] = __float2half(Wr1[(size_t)k * F1 + n]);
    } else if (i < 2 * S1 + S2) {
        int j = i - 2 * S1, n = j / F1, k = j % F1;
        w2l[j] = __float2half(Wl2[(size_t)k * OUTC + n]);
    } else if (i < 2 * S1 + 2 * S2) {
        int j = i - 2 * S1 - S2, n = j / F1, k = j % F1;
        w2r[j] = __float2half(Wr2[(size_t)k * OUTC + n]);
    }
    if (i < N1 + 1) deg1[i] = 0;
    if (i < N2 + 1) deg2[i] = 0;
    if (i < 128) flags[i] = 0;
}

// ---------------- fused layer-1 GEMM + edge counting (one launch) -----------
// blocks [0, NGEMM1): GEMM over 128 rows of x. blocks [NGEMM1, +NCNT): count.
#define ASTRIDE 136
__global__ __launch_bounds__(256) void gemm1_fused_k(
    const float* __restrict__ x,
    const __half* __restrict__ w1l, const __half* __restrict__ w1r,
    const float* __restrict__ bl1, const float* __restrict__ br1,
    __half* __restrict__ xl, __half* __restrict__ xr, int nr_blocks,
    const int* __restrict__ dst1, const int* __restrict__ dst2,
    int* __restrict__ deg1, int* __restrict__ deg2)
{
    int tid = threadIdx.x;
    if (blockIdx.y >= NGEMM1) {
        // -------- counting role: 4 int4 per thread --------
        int cb = blockIdx.y - NGEMM1;
        #pragma unroll
        for (int u = 0; u < 4; u++) {
            int i = cb * 1024 + u * 256 + tid;
            if (i < E1 / 4) {
                int4 d = ((const int4*)dst1)[i];
                atomicAdd(&deg1[d.x], 1); atomicAdd(&deg1[d.y], 1);
                atomicAdd(&deg1[d.z], 1); atomicAdd(&deg1[d.w], 1);
            } else if (i < E1 / 4 + E2 / 4) {
                int4 d = ((const int4*)dst2)[i - E1 / 4];
                atomicAdd(&deg2[d.x], 1); atomicAdd(&deg2[d.y], 1);
                atomicAdd(&deg2[d.z], 1); atomicAdd(&deg2[d.w], 1);
            }
        }
        return;
    }

    extern __shared__ __half sm[];
    __half* As = sm;
    __half* Bs = sm + 128 * ASTRIDE;

    int lane = tid & 31, wid = tid >> 5;
    int wm = wid >> 1, wn = wid & 1;
    size_t m0 = (size_t)blockIdx.y * 128;

    uint32_t asb = smem_to_u32(As), bsb = smem_to_u32(Bs);

    for (int i = tid; i < 2048; i += 256) {
        int r = i >> 4, c8 = (i & 15) * 8;
        const float* p = &x[(m0 + r) * INC + c8];
        float4 v0 = *(const float4*)p;
        float4 v1 = *(const float4*)(p + 4);
        __half2 h[4] = {__floats2half2_rn(v0.x, v0.y), __floats2half2_rn(v0.z, v0.w),
                        __floats2half2_rn(v1.x, v1.y), __floats2half2_rn(v1.z, v1.w)};
        *(uint4*)&As[r * ASTRIDE + c8] = *(uint4*)h;
    }

    int npass = (blockIdx.y < (unsigned)nr_blocks) ? 4 : 2;
    for (int pass = 0; pass < npass; pass++) {
        const __half* B = (pass < 2) ? w1l : w1r;
        const float* bias = (pass < 2) ? bl1 : br1;
        __half* dst = (pass < 2) ? xl : xr;
        int nb = (pass & 1) * 128;

        __syncthreads();
        for (int i = tid; i < 2048; i += 256) {
            int r = i >> 4, c8 = (i & 15) * 8;
            *(uint4*)&Bs[r * ASTRIDE + c8] = *(const uint4*)&B[(size_t)(nb + r) * INC + c8];
        }
        __syncthreads();

        float c[2][8][4] = {};
        #pragma unroll
        for (int kk = 0; kk < 8; kk++) {
            uint32_t af[2][4], bf[8][2];
            #pragma unroll
            for (int mt = 0; mt < 2; mt++) {
                int row = wm * 32 + mt * 16 + (lane & 7) + ((lane >> 3) & 1) * 8;
                int col = kk * 16 + (lane >> 4) * 8;
                ldm_x4(af[mt], asb + (uint32_t)(row * ASTRIDE + col) * 2);
            }
            #pragma unroll
            for (int nt = 0; nt < 8; nt++) {
                int row = wn * 64 + nt * 8 + (lane & 7);
                int col = kk * 16 + ((lane >> 3) & 1) * 8;
                ldm_x2(bf[nt], bsb + (uint32_t)(row * ASTRIDE + col) * 2);
            }
            #pragma unroll
            for (int mt = 0; mt < 2; mt++)
                #pragma unroll
                for (int nt = 0; nt < 8; nt++)
                    mma16816(c[mt][nt], af[mt], bf[nt]);
        }

        #pragma unroll
        for (int mt = 0; mt < 2; mt++) {
            size_t r0 = m0 + wm * 32 + mt * 16 + (lane >> 2);
            #pragma unroll
            for (int nt = 0; nt < 8; nt++) {
                int col = nb + wn * 64 + nt * 8 + (lane & 3) * 2;
                float bx = bias[col], by = bias[col + 1];
                *(__half2*)&dst[r0 * F1 + col] =
                    __floats2half2_rn(c[mt][nt][0] + bx, c[mt][nt][1] + by);
                *(__half2*)&dst[(r0 + 8) * F1 + col] =
                    __floats2half2_rn(c[mt][nt][2] + bx, c[mt][nt][3] + by);
            }
        }
    }
}

// ---------------- one-launch two-level scan with warp-parallel lookback -----
// 95 blocks (<=148 SMs, all resident wave-1 -> spin is deadlock-free).
// blocks [0,NB1) scan deg1->off1 (+cur1); blocks [NB1,NB1+NB2) deg2->off2 (+cur2).
__global__ __launch_bounds__(1024) void scan_lb_k(
    const int* __restrict__ deg1, int* __restrict__ off1, int* __restrict__ cur1,
    const int* __restrict__ deg2, int* __restrict__ off2, int* __restrict__ cur2,
    int* __restrict__ bsums, int* __restrict__ flags)
{
    __shared__ int s[1024];
    __shared__ int sprefix;
    int b = blockIdx.x;
    const int* in; int* out; int* cur; int n; int nnode; int seg0;
    if (b < NB1) { in = deg1; out = off1; cur = cur1; n = N1 + 1; nnode = N1; seg0 = 0; }
    else         { in = deg2; out = off2; cur = cur2; n = N2 + 1; nnode = N2; seg0 = NB1; }
    int bi = b - seg0;
    int tid = threadIdx.x;
    int i = bi * 1024 + tid;
    int v = (i < n) ? in[i] : 0;
    s[tid] = v;
    __syncthreads();
    for (int d = 1; d < 1024; d <<= 1) {
        int t = (tid >= d) ? s[tid - d] : 0;
        __syncthreads();
        s[tid] += t;
        __syncthreads();
    }
    // publish aggregate
    if (tid == 0) {
        bsums[b] = s[1023];
        __threadfence();
        atomicExch(&flags[b], 1);
    }
    // lookback: sum aggregates of prior blocks in this segment (warp 0)
    if (tid < 32) {
        int p = 0;
        for (int j = seg0 + tid; j < b; j += 32) {
            while (atomicAdd(&flags[j], 0) == 0) {}
            p += atomicAdd(&bsums[j], 0);
        }
        #pragma unroll
        for (int o = 16; o; o >>= 1) p += __shfl_xor_sync(0xffffffffu, p, o);
        if (tid == 0) sprefix = p;
    }
    __syncthreads();
    int pre = sprefix;
    if (i < n) {
        int e = pre + s[tid] - v;       // exclusive prefix
        out[i] = e;
        if (i < nnode) cur[i] = e;
    }
}

__global__ void scatter_both_k(const int* __restrict__ src1, const int* __restrict__ dst1,
                               int* __restrict__ cur1, int* __restrict__ csr1,
                               const int* __restrict__ src2, const int* __restrict__ dst2,
                               int* __restrict__ cur2, int* __restrict__ csr2) {
    int i = blockIdx.x * blockDim.x + threadIdx.x;
    if (i < E1) {
        int d = dst1[i];
        int pos = atomicAdd(&cur1[d], 1);
        csr1[pos] = src1[i];
    } else if (i < E1 + E2) {
        int j = i - E1;
        int d = dst2[j];
        int pos = atomicAdd(&cur2[d], 1);
        csr2[pos] = src2[j];
    }
}

// ---------------- merged layer-2 GEMM ----------------------------------------
__global__ __launch_bounds__(256) void hmma_gemm2_k(
    const __half* __restrict__ A,
    const __half* __restrict__ BtL, const __half* __restrict__ BtR,
    const float* __restrict__ biasL, const float* __restrict__ biasR,
    float* __restrict__ CL, float* __restrict__ CR, int split)
{
    constexpr int BN = 48, WN = 24, NT = 3, K_DIM = F1, N_OUT = OUTC;
    __shared__ __half As[128][40];
    __shared__ __half Bs[BN][40];

    int tid = threadIdx.x, lane = tid & 31, wid = tid >> 5;
    int wm = wid >> 1, wn = wid & 1;

    const __half* Bt; const float* bias; float* C; size_t m0;
    if ((int)blockIdx.y < split) { Bt = BtL; bias = biasL; C = CL; m0 = (size_t)blockIdx.y * 128; }
    else                          { Bt = BtR; bias = biasR; C = CR; m0 = (size_t)(blockIdx.y - split) * 128; }

    uint32_t asb = smem_to_u32(As), bsb = smem_to_u32(Bs);
    float c[2][NT][4] = {};

    for (int k0 = 0; k0 < K_DIM; k0 += 32) {
        #pragma unroll
        for (int i = tid; i < 512; i += 256) {
            int r = i >> 2, cv = i & 3;
            *(uint4*)&As[r][cv * 8] = *(const uint4*)&A[(m0 + r) * K_DIM + k0 + cv * 8];
        }
        #pragma unroll
        for (int i = tid; i < BN * 4; i += 256) {
            int r = i >> 2, cv = i & 3;
            *(uint4*)&Bs[r][cv * 8] = *(const uint4*)&Bt[(size_t)r * K_DIM + k0 + cv * 8];
        }
        __syncthreads();

        #pragma unroll
        for (int kk = 0; kk < 2; kk++) {
            uint32_t af[2][4], bf[NT][2];
            #pragma unroll
            for (int mt = 0; mt < 2; mt++) {
                int row = wm * 32 + mt * 16 + (lane & 7) + ((lane >> 3) & 1) * 8;
                int col = kk * 16 + (lane >> 4) * 8;
                ldm_x4(af[mt], asb + (uint32_t)(row * 40 + col) * 2);
            }
            #pragma unroll
            for (int nt = 0; nt < NT; nt++) {
                int row = wn * WN + nt * 8 + (lane & 7);
                int col = kk * 16 + ((lane >> 3) & 1) * 8;
                ldm_x2(bf[nt], bsb + (uint32_t)(row * 40 + col) * 2);
            }
            #pragma unroll
            for (int mt = 0; mt < 2; mt++)
                #pragma unroll
                for (int nt = 0; nt < NT; nt++)
                    mma16816(c[mt][nt], af[mt], bf[nt]);
        }
        __syncthreads();
    }

    #pragma unroll
    for (int mt = 0; mt < 2; mt++) {
        size_t r0 = m0 + wm * 32 + mt * 16 + (lane >> 2);
        #pragma unroll
        for (int nt = 0; nt < NT; nt++) {
            int col = wn * WN + nt * 8 + (lane & 3) * 2;
            float bx = bias[col], by = bias[col + 1];
            float2 o0 = {c[mt][nt][0] + bx, c[mt][nt][1] + by};
            float2 o1 = {c[mt][nt][2] + bx, c[mt][nt][3] + by};
            *(float2*)&C[r0 * N_OUT + col] = o0;
            *(float2*)&C[(r0 + 8) * N_OUT + col] = o1;
        }
    }
}

__device__ __forceinline__ float leaky(float v) { return v > 0.f ? v : 0.2f * v; }

__device__ __forceinline__ float4 ldrow_h4(const __half* p) {
    uint2 u = *(const uint2*)p;
    __half2 h01 = *(__half2*)&u.x;
    __half2 h23 = *(__half2*)&u.y;
    float2 f01 = __half22float2(h01);
    float2 f23 = __half22float2(h23);
    return make_float4(f01.x, f01.y, f23.x, f23.y);
}

// ---------------- layer-1 aggregation ----------------------------------------
__global__ __launch_bounds__(64) void agg1_k(
    const __half* __restrict__ xl, const __half* __restrict__ xr,
    const int* __restrict__ csr, const int* __restrict__ off,
    const float* __restrict__ att, const float* __restrict__ bias,
    __half* __restrict__ out)
{
    int d = blockIdx.x;
    int t = threadIdx.x;
    int base = t * 4;
    float4 attv = *(const float4*)(att + base);
    float4 xrv  = ldrow_h4(xr + (size_t)d * F1 + base);

    float m = -3e38f, l = 0.f;
    float4 acc = {0.f, 0.f, 0.f, 0.f};

    int k0 = off[d], k1 = off[d + 1];
    int k = k0;
    for (; k + 4 <= k1; k += 4) {
        int s0 = csr[k], s1 = csr[k + 1], s2 = csr[k + 2], s3 = csr[k + 3];
        float4 xa = ldrow_h4(xl + (size_t)s0 * F1 + base);
        float4 xb = ldrow_h4(xl + (size_t)s1 * F1 + base);
        float4 xc = ldrow_h4(xl + (size_t)s2 * F1 + base);
        float4 xd = ldrow_h4(xl + (size_t)s3 * F1 + base);
        float pa = leaky(xa.x + xrv.x) * attv.x + leaky(xa.y + xrv.y) * attv.y
                 + leaky(xa.z + xrv.z) * attv.z + leaky(xa.w + xrv.w) * attv.w;
        float pb = leaky(xb.x + xrv.x) * attv.x + leaky(xb.y + xrv.y) * attv.y
                 + leaky(xb.z + xrv.z) * attv.z + leaky(xb.w + xrv.w) * attv.w;
        float pc = leaky(xc.x + xrv.x) * attv.x + leaky(xc.y + xrv.y) * attv.y
                 + leaky(xc.z + xrv.z) * attv.z + leaky(xc.w + xrv.w) * attv.w;
        float pd = leaky(xd.x + xrv.x) * attv.x + leaky(xd.y + xrv.y) * attv.y
                 + leaky(xd.z + xrv.z) * attv.z + leaky(xd.w + xrv.w) * attv.w;
        #pragma unroll
        for (int o = 8; o; o >>= 1) {
            pa += __shfl_xor_sync(0xffffffffu, pa, o);
            pb += __shfl_xor_sync(0xffffffffu, pb, o);
            pc += __shfl_xor_sync(0xffffffffu, pc, o);
            pd += __shfl_xor_sync(0xffffffffu, pd, o);
        }
        float mn = fmaxf(fmaxf(m, fmaxf(pa, pb)), fmaxf(pc, pd));
        float sc = __expf(m - mn);
        float ea = __expf(pa - mn);
        float eb = __expf(pb - mn);
        float ec = __expf(pc - mn);
        float ed = __expf(pd - mn);
        l = l * sc + ea + eb + ec + ed;
        acc.x = acc.x * sc + ea * xa.x + eb * xb.x + ec * xc.x + ed * xd.x;
        acc.y = acc.y * sc + ea * xa.y + eb * xb.y + ec * xc.y + ed * xd.y;
        acc.z = acc.z * sc + ea * xa.z + eb * xb.z + ec * xc.z + ed * xd.z;
        acc.w = acc.w * sc + ea * xa.w + eb * xb.w + ec * xc.w + ed * xd.w;
        m = mn;
    }
    for (; k < k1; k++) {
        int s = csr[k];
        float4 xv = ldrow_h4(xl + (size_t)s * F1 + base);
        float p = leaky(xv.x + xrv.x) * attv.x + leaky(xv.y + xrv.y) * attv.y
                + leaky(xv.z + xrv.z) * attv.z + leaky(xv.w + xrv.w) * attv.w;
        #pragma unroll
        for (int o = 8; o; o >>= 1) p += __shfl_xor_sync(0xffffffffu, p, o);
        float mn = fmaxf(m, p);
        float sc = __expf(m - mn);
        float pe = __expf(p - mn);
        l = l * sc + pe;
        acc.x = acc.x * sc + pe * xv.x;
        acc.y = acc.y * sc + pe * xv.y;
        acc.z = acc.z * sc + pe * xv.z;
        acc.w = acc.w * sc + pe * xv.w;
        m = mn;
    }
    float inv = 1.f / (l + 1e-16f);
    float4 bv = *(const float4*)(bias + base);
    float ox = fmaxf(acc.x * inv + bv.x, 0.f);
    float oy = fmaxf(acc.y * inv + bv.y, 0.f);
    float oz = fmaxf(acc.z * inv + bv.z, 0.f);
    float ow = fmaxf(acc.w * inv + bv.w, 0.f);
    __half2* hp = (__half2*)(out + (size_t)d * F1 + base);
    hp[0] = __floats2half2_rn(ox, oy);
    hp[1] = __floats2half2_rn(oz, ow);
}

// ---------------- layer-2 aggregation + fused log_softmax -------------------
__global__ __launch_bounds__(128) void agg2_k(
    const float* __restrict__ xl, const float* __restrict__ xr,
    const int* __restrict__ csr, const int* __restrict__ off,
    const float* __restrict__ att, const float* __restrict__ bias,
    float* __restrict__ out, int n)
{
    int w = (blockIdx.x * blockDim.x + threadIdx.x) >> 5;
    if (w >= n) return;
    int lane = threadIdx.x & 31;
    bool lo = (lane < 16);
    float a0 = att[lane];
    float a1 = lo ? att[32 + lane] : 0.f;
    float xr0 = xr[(size_t)w * OUTC + lane];
    float xr1 = lo ? xr[(size_t)w * OUTC + 32 + lane] : 0.f;

    float m = -3e38f, l = 0.f, acc0 = 0.f, acc1 = 0.f;
    int k0 = off[w], k1 = off[w + 1];
    for (int k = k0; k < k1; k++) {
        int s = csr[k];
        float x0 = xl[(size_t)s * OUTC + lane];
        float x1 = lo ? xl[(size_t)s * OUTC + 32 + lane] : 0.f;
        float p = leaky(x0 + xr0) * a0 + leaky(x1 + xr1) * a1;
        #pragma unroll
        for (int o = 16; o; o >>= 1) p += __shfl_xor_sync(0xffffffffu, p, o);
        float mn = fmaxf(m, p);
        float sc = __expf(m - mn);
        float pe = __expf(p - mn);
        l = l * sc + pe;
        acc0 = acc0 * sc + pe * x0;
        acc1 = acc1 * sc + pe * x1;
        m = mn;
    }
    float inv = 1.f / (l + 1e-16f);
    float v0 = acc0 * inv + bias[lane];
    float v1 = lo ? (acc1 * inv + bias[32 + lane]) : -3e38f;

    float mx = fmaxf(v0, v1);
    #pragma unroll
    for (int o = 16; o; o >>= 1) mx = fmaxf(mx, __shfl_xor_sync(0xffffffffu, mx, o));
    float se = __expf(v0 - mx) + (lo ? __expf(v1 - mx) : 0.f);
    #pragma unroll
    for (int o = 16; o; o >>= 1) se += __shfl_xor_sync(0xffffffffu, se, o);
    float lse = logf(se) + mx;
    out[(size_t)w * OUTC + lane] = v0 - lse;
    if (lo) out[(size_t)w * OUTC + 32 + lane] = v1 - lse;
}

// ---------------- host orchestration ----------------------------------------
extern "C" void kernel_launch(void* const* d_in, const int* in_sizes, int n_in,
                              void* d_out, int out_size)
{
    const float* x     = (const float*)d_in[0];
    const float* Wl1   = (const float*)d_in[1];
    const float* bl1   = (const float*)d_in[2];
    const float* Wr1   = (const float*)d_in[3];
    const float* br1   = (const float*)d_in[4];
    const float* att1  = (const float*)d_in[5];
    const float* bias1 = (const float*)d_in[6];
    const float* Wl2   = (const float*)d_in[7];
    const float* bl2   = (const float*)d_in[8];
    const float* Wr2   = (const float*)d_in[9];
    const float* br2   = (const float*)d_in[10];
    const float* att2  = (const float*)d_in[11];
    const float* bias2 = (const float*)d_in[12];
    const int* src1    = (const int*)d_in[13];
    const int* dst1    = (const int*)d_in[14];
    const int* src2    = (const int*)d_in[15];
    const int* dst2    = (const int*)d_in[16];
    float* out = (float*)d_out;

    float *xl2, *xr2;
    __half *xl1h, *xr1h, *hh, *w1l, *w1r, *w2l, *w2r;
    int *deg1, *off1, *cur1, *csr1, *deg2, *off2, *cur2, *csr2, *bsums, *flags;
    cudaGetSymbolAddress((void**)&xl1h, g_xl1h);
    cudaGetSymbolAddress((void**)&xr1h, g_xr1h);
    cudaGetSymbolAddress((void**)&xl2, g_xl2);
    cudaGetSymbolAddress((void**)&xr2, g_xr2);
    cudaGetSymbolAddress((void**)&hh,  g_hh);
    cudaGetSymbolAddress((void**)&w1l, g_w1l);
    cudaGetSymbolAddress((void**)&w1r, g_w1r);
    cudaGetSymbolAddress((void**)&w2l, g_w2l);
    cudaGetSymbolAddress((void**)&w2r, g_w2r);
    cudaGetSymbolAddress((void**)&deg1, g_deg1);
    cudaGetSymbolAddress((void**)&off1, g_off1);
    cudaGetSymbolAddress((void**)&cur1, g_cur1);
    cudaGetSymbolAddress((void**)&csr1, g_csr1);
    cudaGetSymbolAddress((void**)&deg2, g_deg2);
    cudaGetSymbolAddress((void**)&off2, g_off2);
    cudaGetSymbolAddress((void**)&cur2, g_cur2);
    cudaGetSymbolAddress((void**)&csr2, g_csr2);
    cudaGetSymbolAddress((void**)&bsums, g_bsums);
    cudaGetSymbolAddress((void**)&flags, g_flags);

    const int SMEMF = 2 * 128 * ASTRIDE * (int)sizeof(__half);
    cudaFuncSetAttribute(gemm1_fused_k, cudaFuncAttributeMaxDynamicSharedMemorySize, SMEMF);

    // 1. prep: weight transposes + zero deg/flags
    prep_k<<<(N1 + 1 + 255) / 256, 256>>>(Wl1, Wr1, Wl2, Wr2, w1l, w1r, w2l, w2r,
                                          deg1, deg2, flags);

    // 2. layer-1 GEMM + hidden edge counting
    gemm1_fused_k<<<dim3(1, NGEMM1 + NCNT), 256, SMEMF>>>(
        x, w1l, w1r, bl1, br1, xl1h, xr1h, N1 / 128, dst1, dst2, deg1, deg2);

    // 3. one-launch scan (both layers) with lookback
    scan_lb_k<<<NB1 + NB2, 1024>>>(deg1, off1, cur1, deg2, off2, cur2, bsums, flags);

    // 4. scatter both layers
    scatter_both_k<<<(E1 + E2 + 255) / 256, 256>>>(src1, dst1, cur1, csr1,
                                                   src2, dst2, cur2, csr2);

    // 5. layer-1 aggregation
    agg1_k<<<N1, 64>>>(xl1h, xr1h, csr1, off1, att1, bias1, hh);

    // 6. merged layer-2 GEMMs
    hmma_gemm2_k<<<dim3(1, N1 / 128 + N2 / 128), 256>>>(hh, w2l, w2r, bl2, br2,
                                                        xl2, xr2, N1 / 128);

    // 7. layer-2 aggregation + log_softmax
    agg2_k<<<N2 / 4, 128>>>(xl2, xr2, csr2, off2, att2, bias2, out, N2);
}